// round 1
// baseline (speedup 1.0000x reference)
#include <cuda_runtime.h>
#include <math.h>

// Problem constants: B=2048, D=1024, H=1024
// Fused formulation:
//   A  = [x, h_prev, x^2, h_prev^2]                      (2048 x 4096)
//   Bf = [W_mu; U_mu; eps*sp2(W_rho); eps*sp2(U_rho)]    (4096 x 2048)  cols: [0,1024)=u gate, [1024,2048)=h gate
//   arg = A @ Bf + bias,  u=sigmoid(arg_u), hp=tanh(arg_h), out = u*h_prev + (1-u)*hp
// (r gate is dead code in the reference.)

#define KDIM 4096
#define NDIM 2048
#define MDIM 2048

// Scratch (allocation-free rule: __device__ globals)
__device__ float g_A[(size_t)MDIM * KDIM];     // 32 MB
__device__ float g_Bf[(size_t)KDIM * NDIM];    // 32 MB
__device__ float g_bias[NDIM];
__device__ float g_C[(size_t)MDIM * NDIM];     // 16 MB

__device__ __forceinline__ float softplusf(float r) {
    // r ~ N(-4,1); stable for all fp32 inputs
    return (r > 20.0f) ? r : log1pf(expf(r));
}

// ---------------------------------------------------------------------------
// Preprocessing kernels
// ---------------------------------------------------------------------------

__global__ void build_A_kernel(const float* __restrict__ x, const float* __restrict__ h) {
    int idx = blockIdx.x * blockDim.x + threadIdx.x;   // over 2048*1024
    int b = idx >> 10;
    int k = idx & 1023;
    float xv = x[idx];
    float hv = h[idx];
    float* row = g_A + (size_t)b * KDIM;
    row[k]        = xv;
    row[1024 + k] = hv;
    row[2048 + k] = xv * xv;
    row[3072 + k] = hv * hv;
}

__global__ void build_B_kernel(const float* __restrict__ W_mu, const float* __restrict__ W_rho,
                               const float* __restrict__ U_mu, const float* __restrict__ U_rho,
                               const float* __restrict__ u_eps, const float* __restrict__ h_eps) {
    int idx = blockIdx.x * blockDim.x + threadIdx.x;   // over 4096*2048, idx = k*2048 + j
    int j = idx & 2047;
    int k = idx >> 11;
    int g  = j >> 10;            // 0 = u gate, 1 = h gate
    int jj = j & 1023;
    int gcol = (g + 1) * 1024 + jj;   // global column in the 3072-wide weight matrices
    float val;
    if (k < 1024) {
        val = W_mu[k * 3072 + gcol];
    } else if (k < 2048) {
        val = U_mu[(k - 1024) * 3072 + gcol];
    } else {
        float eps = g ? h_eps[jj] : u_eps[jj];
        float rho = (k < 3072) ? W_rho[(k - 2048) * 3072 + gcol]
                               : U_rho[(k - 3072) * 3072 + gcol];
        float s = softplusf(rho);
        val = eps * s * s;
    }
    g_Bf[idx] = val;
}

__global__ void build_bias_kernel(const float* __restrict__ b_mu, const float* __restrict__ b_rho,
                                  const float* __restrict__ u_eps, const float* __restrict__ h_eps) {
    int j = blockIdx.x * blockDim.x + threadIdx.x;
    if (j >= NDIM) return;
    int g  = j >> 10;
    int jj = j & 1023;
    int gcol = (g + 1) * 1024 + jj;
    float eps = g ? h_eps[jj] : u_eps[jj];
    g_bias[j] = b_mu[gcol] + eps * softplusf(b_rho[gcol]);   // bias sig is softplus, NOT squared
}

// ---------------------------------------------------------------------------
// SGEMM 2048x2048x4096, fp32, packed f32x2 FMA, double-buffered 128x128x16
// ---------------------------------------------------------------------------

#define BM 128
#define BN 128
#define BK 16

__device__ __forceinline__ unsigned long long pk2(float lo, float hi) {
    unsigned long long r;
    asm("mov.b64 %0, {%1, %2};" : "=l"(r)
        : "r"(__float_as_uint(lo)), "r"(__float_as_uint(hi)));
    return r;
}
__device__ __forceinline__ void fma2(unsigned long long& d, unsigned long long a, unsigned long long b) {
    asm("fma.rn.f32x2 %0, %1, %2, %0;" : "+l"(d) : "l"(a), "l"(b));
}
__device__ __forceinline__ void upk(unsigned long long v, float& lo, float& hi) {
    unsigned int a, b;
    asm("mov.b64 {%0, %1}, %2;" : "=r"(a), "=r"(b) : "l"(v));
    lo = __uint_as_float(a);
    hi = __uint_as_float(b);
}

__global__ __launch_bounds__(256, 2) void sgemm_kernel() {
    __shared__ float As[2][BK * BM];
    __shared__ float Bs[2][BK * BN];

    const float* __restrict__ A  = g_A;
    const float* __restrict__ Bm = g_Bf;

    const int tid = threadIdx.x;
    const int bn = blockIdx.x, bm = blockIdx.y;
    const int tx = tid & 15, ty = tid >> 4;

    // global-load mapping
    const int aRow = tid >> 2;          // 0..63
    const int aCol = (tid & 3) << 2;    // 0,4,8,12
    const int bRow = tid >> 5;          // 0..7
    const int bCol = (tid & 31) << 2;   // 0..124

    const float* Ag = A  + (size_t)(bm * BM + aRow) * KDIM + aCol;
    const float* Bg = Bm + (size_t)bRow * NDIM + bn * BN + bCol;

    float4 pa0, pa1, pb0, pb1;

    // prefetch stage 0
    pa0 = *(const float4*)(Ag);
    pa1 = *(const float4*)(Ag + (size_t)64 * KDIM);
    pb0 = *(const float4*)(Bg);
    pb1 = *(const float4*)(Bg + (size_t)8 * NDIM);

    As[0][(aCol + 0) * BM + aRow]      = pa0.x;
    As[0][(aCol + 1) * BM + aRow]      = pa0.y;
    As[0][(aCol + 2) * BM + aRow]      = pa0.z;
    As[0][(aCol + 3) * BM + aRow]      = pa0.w;
    As[0][(aCol + 0) * BM + aRow + 64] = pa1.x;
    As[0][(aCol + 1) * BM + aRow + 64] = pa1.y;
    As[0][(aCol + 2) * BM + aRow + 64] = pa1.z;
    As[0][(aCol + 3) * BM + aRow + 64] = pa1.w;
    *(float4*)&Bs[0][bRow * BN + bCol]       = pb0;
    *(float4*)&Bs[0][(bRow + 8) * BN + bCol] = pb1;
    __syncthreads();

    unsigned long long acc[8][4];
#pragma unroll
    for (int i = 0; i < 8; ++i)
#pragma unroll
        for (int jp = 0; jp < 4; ++jp) acc[i][jp] = 0ull;

    const int KT = KDIM / BK;  // 256
    for (int kt = 0; kt < KT; ++kt) {
        const int cur = kt & 1;
        if (kt + 1 < KT) {
            const float* Ag2 = Ag + (size_t)(kt + 1) * BK;
            const float* Bg2 = Bg + (size_t)(kt + 1) * BK * NDIM;
            pa0 = *(const float4*)(Ag2);
            pa1 = *(const float4*)(Ag2 + (size_t)64 * KDIM);
            pb0 = *(const float4*)(Bg2);
            pb1 = *(const float4*)(Bg2 + (size_t)8 * NDIM);
        }
#pragma unroll
        for (int k = 0; k < BK; ++k) {
            const float4 av0 = *(const float4*)&As[cur][k * BM + ty * 8];
            const float4 av1 = *(const float4*)&As[cur][k * BM + ty * 8 + 4];
            const float4 bv0 = *(const float4*)&Bs[cur][k * BN + tx * 8];
            const float4 bv1 = *(const float4*)&Bs[cur][k * BN + tx * 8 + 4];
            const unsigned long long bp0 = pk2(bv0.x, bv0.y);
            const unsigned long long bp1 = pk2(bv0.z, bv0.w);
            const unsigned long long bp2 = pk2(bv1.x, bv1.y);
            const unsigned long long bp3 = pk2(bv1.z, bv1.w);
            const float am[8] = {av0.x, av0.y, av0.z, av0.w, av1.x, av1.y, av1.z, av1.w};
#pragma unroll
            for (int i = 0; i < 8; ++i) {
                const unsigned long long ap = pk2(am[i], am[i]);
                fma2(acc[i][0], ap, bp0);
                fma2(acc[i][1], ap, bp1);
                fma2(acc[i][2], ap, bp2);
                fma2(acc[i][3], ap, bp3);
            }
        }
        if (kt + 1 < KT) {
            const int nxt = (kt + 1) & 1;
            As[nxt][(aCol + 0) * BM + aRow]      = pa0.x;
            As[nxt][(aCol + 1) * BM + aRow]      = pa0.y;
            As[nxt][(aCol + 2) * BM + aRow]      = pa0.z;
            As[nxt][(aCol + 3) * BM + aRow]      = pa0.w;
            As[nxt][(aCol + 0) * BM + aRow + 64] = pa1.x;
            As[nxt][(aCol + 1) * BM + aRow + 64] = pa1.y;
            As[nxt][(aCol + 2) * BM + aRow + 64] = pa1.z;
            As[nxt][(aCol + 3) * BM + aRow + 64] = pa1.w;
            *(float4*)&Bs[nxt][bRow * BN + bCol]       = pb0;
            *(float4*)&Bs[nxt][(bRow + 8) * BN + bCol] = pb1;
            __syncthreads();
        }
    }

    // epilogue: add bias, write C
    const int crow = bm * BM + ty * 8;
    const int ccol = bn * BN + tx * 8;
    float bcol[8];
#pragma unroll
    for (int j = 0; j < 8; ++j) bcol[j] = g_bias[ccol + j];
#pragma unroll
    for (int i = 0; i < 8; ++i) {
        float c[8];
        upk(acc[i][0], c[0], c[1]);
        upk(acc[i][1], c[2], c[3]);
        upk(acc[i][2], c[4], c[5]);
        upk(acc[i][3], c[6], c[7]);
        float4 o0 = make_float4(c[0] + bcol[0], c[1] + bcol[1], c[2] + bcol[2], c[3] + bcol[3]);
        float4 o1 = make_float4(c[4] + bcol[4], c[5] + bcol[5], c[6] + bcol[6], c[7] + bcol[7]);
        float* Cp = g_C + (size_t)(crow + i) * NDIM + ccol;
        *(float4*)(Cp)     = o0;
        *(float4*)(Cp + 4) = o1;
    }
}

// ---------------------------------------------------------------------------
// Final gate combine
// ---------------------------------------------------------------------------

__global__ void epilogue_kernel(const float* __restrict__ h_prev, float* __restrict__ out) {
    int idx = blockIdx.x * blockDim.x + threadIdx.x;   // over 2048*1024
    int b = idx >> 10;
    int j = idx & 1023;
    float au = g_C[(size_t)b * NDIM + j];
    float ah = g_C[(size_t)b * NDIM + 1024 + j];
    float u  = 1.0f / (1.0f + expf(-au));
    float hp = tanhf(ah);
    out[idx] = u * h_prev[idx] + (1.0f - u) * hp;
}

// ---------------------------------------------------------------------------
// Launch
// ---------------------------------------------------------------------------

extern "C" void kernel_launch(void* const* d_in, const int* in_sizes, int n_in,
                              void* d_out, int out_size) {
    const float* x      = (const float*)d_in[0];
    const float* h_prev = (const float*)d_in[1];
    const float* W_mu   = (const float*)d_in[2];
    const float* W_rho  = (const float*)d_in[3];
    const float* U_mu   = (const float*)d_in[4];
    const float* U_rho  = (const float*)d_in[5];
    const float* b_mu   = (const float*)d_in[6];
    const float* b_rho  = (const float*)d_in[7];
    // d_in[8] = r_eps : unused (r gate is dead in the reference)
    const float* u_eps  = (const float*)d_in[9];
    const float* h_eps  = (const float*)d_in[10];
    float* out = (float*)d_out;

    build_A_kernel<<<(MDIM * 1024) / 256, 256>>>(x, h_prev);
    build_B_kernel<<<(KDIM * NDIM) / 256, 256>>>(W_mu, W_rho, U_mu, U_rho, u_eps, h_eps);
    build_bias_kernel<<<(NDIM + 255) / 256, 256>>>(b_mu, b_rho, u_eps, h_eps);

    dim3 grid(NDIM / BN, MDIM / BM);   // 16 x 16
    sgemm_kernel<<<grid, 256>>>();

    epilogue_kernel<<<(MDIM * 1024) / 256, 256>>>(h_prev, out);
}

// round 4
// speedup vs baseline: 2.2382x; 2.2382x over previous
#include <cuda_runtime.h>
#include <cuda_bf16.h>
#include <math.h>
#include <stdint.h>

// B=2048, D=H=1024.
// Fused: A=[x, h, x^2, h^2] (2048x4096),
//        Bt[n,k], n=2*j+g interleaved (g=0:u gate, 1:h gate), from
//        [W_mu;U_mu;eps*sp2(W_rho);eps*sp2(U_rho)] columns [1024,3072).
// arg = A @ Bt^T + bias ; u=sigmoid, hp=tanh, out = u*h_prev + (1-u)*hp.
// (r gate is dead code in the reference.)
// GEMM: split-precision bf16 on legacy mma.sync (m16n8k16):
//   D = Ah*Bh + Al*Bh + Ah*Bl, fp32 accum in registers.

#define MDIM 2048
#define NDIM 2048
#define KDIM 4096
#define HDIM 1024

__device__ __align__(128) __nv_bfloat16 g_A_hi[(size_t)MDIM * KDIM];
__device__ __align__(128) __nv_bfloat16 g_A_lo[(size_t)MDIM * KDIM];
__device__ __align__(128) __nv_bfloat16 g_B_hi[(size_t)NDIM * KDIM];
__device__ __align__(128) __nv_bfloat16 g_B_lo[(size_t)NDIM * KDIM];
__device__ float g_bias[NDIM];

__device__ __forceinline__ float softplusf(float r) {
    return (r > 20.0f) ? r : log1pf(expf(r));
}

__device__ __forceinline__ void split_store(float v, __nv_bfloat16* hi, __nv_bfloat16* lo) {
    __nv_bfloat16 h = __float2bfloat16(v);
    *hi = h;
    *lo = __float2bfloat16(v - __bfloat162float(h));
}

// ---------------------------------------------------------------------------
// Preprocessing
// ---------------------------------------------------------------------------

__global__ void build_A_kernel(const float* __restrict__ x, const float* __restrict__ h) {
    int idx = blockIdx.x * 256 + threadIdx.x;   // 2048*1024
    int b = idx >> 10;
    int k = idx & 1023;
    float xv = x[idx];
    float hv = h[idx];
    size_t base = (size_t)b * KDIM;
    split_store(xv,      g_A_hi + base + k,        g_A_lo + base + k);
    split_store(hv,      g_A_hi + base + 1024 + k, g_A_lo + base + 1024 + k);
    split_store(xv * xv, g_A_hi + base + 2048 + k, g_A_lo + base + 2048 + k);
    split_store(hv * hv, g_A_hi + base + 3072 + k, g_A_lo + base + 3072 + k);
}

// Tiled transpose: Bt[n=2*jj+g, k]. grid (128, 32, 2), block (32, 8)
__global__ void build_Bt_kernel(const float* __restrict__ W_mu, const float* __restrict__ W_rho,
                                const float* __restrict__ U_mu, const float* __restrict__ U_rho,
                                const float* __restrict__ u_eps, const float* __restrict__ h_eps) {
    __shared__ float tile[32][33];
    int k0  = blockIdx.x * 32;
    int jj0 = blockIdx.y * 32;
    int g   = blockIdx.z;
    int tx = threadIdx.x, ty = threadIdx.y;
    int gcol = (g + 1) * 1024 + jj0 + tx;
#pragma unroll
    for (int i = 0; i < 4; ++i) {
        int k = k0 + ty + i * 8;
        float v;
        if (k < 1024)       v = W_mu[(size_t)k * 3072 + gcol];
        else if (k < 2048)  v = U_mu[(size_t)(k - 1024) * 3072 + gcol];
        else {
            float rho = (k < 3072) ? W_rho[(size_t)(k - 2048) * 3072 + gcol]
                                   : U_rho[(size_t)(k - 3072) * 3072 + gcol];
            float s = softplusf(rho);
            v = s * s;
        }
        tile[ty + i * 8][tx] = v;
    }
    __syncthreads();
    bool sigreg = (k0 >= 2048);
#pragma unroll
    for (int i = 0; i < 4; ++i) {
        int jj = jj0 + ty + i * 8;
        float v = tile[tx][ty + i * 8];          // source (k0+tx, jj)
        if (sigreg) v *= (g ? h_eps[jj] : u_eps[jj]);
        int n = 2 * jj + g;
        size_t off = (size_t)n * KDIM + k0 + tx;
        split_store(v, g_B_hi + off, g_B_lo + off);
    }
}

__global__ void build_bias_kernel(const float* __restrict__ b_mu, const float* __restrict__ b_rho,
                                  const float* __restrict__ u_eps, const float* __restrict__ h_eps) {
    int n = blockIdx.x * 256 + threadIdx.x;
    if (n >= NDIM) return;
    int jj = n >> 1, g = n & 1;
    int gcol = (g + 1) * 1024 + jj;
    float eps = g ? h_eps[jj] : u_eps[jj];
    g_bias[n] = b_mu[gcol] + eps * softplusf(b_rho[gcol]);
}

// ---------------------------------------------------------------------------
// GEMM: 2048x2048x4096 split-bf16 via mma.sync m16n8k16
// ---------------------------------------------------------------------------

#define BMT 128
#define BNT 256
#define BKC 32
#define KT (KDIM / BKC)          // 128
#define LDT 40                   // padded row, elements (80 bytes)
#define A_TILE (128 * LDT * 2)   // 10240 bytes
#define B_TILE (256 * LDT * 2)   // 20480 bytes
#define STG (2 * A_TILE + 2 * B_TILE)   // 61440 bytes
#define NSTG 3
#define SMEM_BYTES (NSTG * STG)  // 184320 bytes

static __device__ __forceinline__ uint32_t smem_u32(const void* p) {
    uint32_t a;
    asm("{ .reg .u64 t; cvta.to.shared.u64 t, %1; cvt.u32.u64 %0, t; }" : "=r"(a) : "l"(p));
    return a;
}
static __device__ __forceinline__ void cp16(uint32_t saddr, const void* g) {
    asm volatile("cp.async.cg.shared.global [%0], [%1], 16;" :: "r"(saddr), "l"(g));
}
static __device__ __forceinline__ void cp_commit() {
    asm volatile("cp.async.commit_group;" ::: "memory");
}
template <int N> static __device__ __forceinline__ void cp_wait() {
    asm volatile("cp.async.wait_group %0;" :: "n"(N) : "memory");
}
static __device__ __forceinline__ void ldsm4(uint32_t& r0, uint32_t& r1, uint32_t& r2, uint32_t& r3,
                                             uint32_t addr) {
    asm volatile("ldmatrix.sync.aligned.m8n8.x4.shared.b16 {%0,%1,%2,%3}, [%4];"
                 : "=r"(r0), "=r"(r1), "=r"(r2), "=r"(r3) : "r"(addr));
}
static __device__ __forceinline__ void mma16816(float* c, const uint32_t* a, uint32_t b0, uint32_t b1) {
    asm volatile("mma.sync.aligned.m16n8k16.row.col.f32.bf16.bf16.f32 "
                 "{%0,%1,%2,%3}, {%4,%5,%6,%7}, {%8,%9}, {%0,%1,%2,%3};"
                 : "+f"(c[0]), "+f"(c[1]), "+f"(c[2]), "+f"(c[3])
                 : "r"(a[0]), "r"(a[1]), "r"(a[2]), "r"(a[3]), "r"(b0), "r"(b1));
}

__global__ __launch_bounds__(512, 1) void gemm_kernel(const float* __restrict__ h_prev,
                                                      float* __restrict__ out) {
    extern __shared__ char sm[];
    const uint32_t sbase = smem_u32(sm);

    const int tid  = threadIdx.x;
    const int lane = tid & 31, wid = tid >> 5;
    const int warp_m = wid & 3, warp_n = wid >> 2;   // 4 x 4 warps
    const int bm = blockIdx.y, bn = blockIdx.x;

    // global tile base pointers (bytes)
    const char* AhG = (const char*)g_A_hi + (size_t)(bm * BMT) * (KDIM * 2);
    const char* AlG = (const char*)g_A_lo + (size_t)(bm * BMT) * (KDIM * 2);
    const char* BhG = (const char*)g_B_hi + (size_t)(bn * BNT) * (KDIM * 2);
    const char* BlG = (const char*)g_B_lo + (size_t)(bn * BNT) * (KDIM * 2);

    // cp.async per-thread mapping (16B lines; rows padded to 80B in smem)
    const int lr = tid >> 2, ls = tid & 3;
    const uint32_t a_soff = (uint32_t)(lr * 80 + ls * 16);
    const size_t   a_goff = (size_t)lr * (KDIM * 2) + ls * 16;
    const uint32_t b_soff0 = a_soff;
    const size_t   b_goff0 = a_goff;
    const uint32_t b_soff1 = (uint32_t)((lr + 128) * 80 + ls * 16);
    const size_t   b_goff1 = (size_t)(lr + 128) * (KDIM * 2) + ls * 16;

    auto load_chunk = [&](int stage, int kt) {
        const uint32_t st = sbase + stage * STG;
        const size_t kb = (size_t)kt * 64;   // 32 elements * 2B
        cp16(st + 0      + a_soff, AhG + a_goff + kb);
        cp16(st + A_TILE + a_soff, AlG + a_goff + kb);
        cp16(st + 2 * A_TILE          + b_soff0, BhG + b_goff0 + kb);
        cp16(st + 2 * A_TILE          + b_soff1, BhG + b_goff1 + kb);
        cp16(st + 2 * A_TILE + B_TILE + b_soff0, BlG + b_goff0 + kb);
        cp16(st + 2 * A_TILE + B_TILE + b_soff1, BlG + b_goff1 + kb);
        cp_commit();
    };

    float acc[2][8][4];
#pragma unroll
    for (int i = 0; i < 2; ++i)
#pragma unroll
        for (int j = 0; j < 8; ++j)
#pragma unroll
            for (int q = 0; q < 4; ++q) acc[i][j][q] = 0.0f;

    // ldmatrix per-lane base offsets (within a stage)
    const uint32_t aA_off = (uint32_t)((warp_m * 32 + (lane & 15)) * 80 + (lane >> 4) * 16);
    const uint32_t aB_off = (uint32_t)(2 * A_TILE +
                     (warp_n * 64 + ((lane >> 4) << 3) + (lane & 7)) * 80 + ((lane >> 3) & 1) * 16);

    // prologue
    load_chunk(0, 0);
    load_chunk(1, 1);

    for (int kt = 0; kt < KT; ++kt) {
        const int stage = kt % NSTG;
        if (kt == KT - 1) cp_wait<0>(); else cp_wait<1>();
        __syncthreads();
        if (kt + 2 < KT) load_chunk((kt + 2) % NSTG, kt + 2);

        const uint32_t st = sbase + stage * STG;
        const uint32_t aAh = st + aA_off;
        const uint32_t aB  = st + aB_off;

#pragma unroll
        for (int ks = 0; ks < 2; ++ks) {
            const uint32_t ka = ks * 32;   // 16 elements * 2B
            uint32_t ah0[4], ah1[4], al0[4], al1[4];
            ldsm4(ah0[0], ah0[1], ah0[2], ah0[3], aAh + ka);
            ldsm4(ah1[0], ah1[1], ah1[2], ah1[3], aAh + 16 * 80 + ka);
            ldsm4(al0[0], al0[1], al0[2], al0[3], aAh + A_TILE + ka);
            ldsm4(al1[0], al1[1], al1[2], al1[3], aAh + A_TILE + 16 * 80 + ka);
#pragma unroll
            for (int ntp = 0; ntp < 4; ++ntp) {
                uint32_t bh0, bh1, bh2, bh3, bl0, bl1, bl2, bl3;
                ldsm4(bh0, bh1, bh2, bh3, aB + ntp * 16 * 80 + ka);
                ldsm4(bl0, bl1, bl2, bl3, aB + B_TILE + ntp * 16 * 80 + ka);
                const int nt0 = 2 * ntp, nt1 = 2 * ntp + 1;
                mma16816(acc[0][nt0], ah0, bh0, bh1);
                mma16816(acc[1][nt0], ah1, bh0, bh1);
                mma16816(acc[0][nt1], ah0, bh2, bh3);
                mma16816(acc[1][nt1], ah1, bh2, bh3);
                mma16816(acc[0][nt0], al0, bh0, bh1);
                mma16816(acc[1][nt0], al1, bh0, bh1);
                mma16816(acc[0][nt1], al0, bh2, bh3);
                mma16816(acc[1][nt1], al1, bh2, bh3);
                mma16816(acc[0][nt0], ah0, bl0, bl1);
                mma16816(acc[1][nt0], ah1, bl0, bl1);
                mma16816(acc[0][nt1], ah0, bl2, bl3);
                mma16816(acc[1][nt1], ah1, bl2, bl3);
            }
        }
    }

    // Epilogue: adjacent accumulator column pair = (u-gate, h-gate) for one j.
    const int r_base = bm * BMT + warp_m * 32 + (lane >> 2);
#pragma unroll
    for (int mt = 0; mt < 2; ++mt) {
#pragma unroll
        for (int nt = 0; nt < 8; ++nt) {
            const int n0 = bn * BNT + warp_n * 64 + nt * 8 + (lane & 3) * 2;
            const float bu = g_bias[n0];
            const float bh = g_bias[n0 + 1];
            const int j = n0 >> 1;
#pragma unroll
            for (int hlf = 0; hlf < 2; ++hlf) {
                const int row = r_base + mt * 16 + hlf * 8;
                const float au  = acc[mt][nt][hlf * 2]     + bu;
                const float ahv = acc[mt][nt][hlf * 2 + 1] + bh;
                const float u  = 1.0f / (1.0f + __expf(-au));
                const float hp = tanhf(ahv);
                const size_t g = (size_t)row * HDIM + j;
                out[g] = u * h_prev[g] + (1.0f - u) * hp;
            }
        }
    }
}

// ---------------------------------------------------------------------------
// Launch
// ---------------------------------------------------------------------------

extern "C" void kernel_launch(void* const* d_in, const int* in_sizes, int n_in,
                              void* d_out, int out_size) {
    const float* x      = (const float*)d_in[0];
    const float* h_prev = (const float*)d_in[1];
    const float* W_mu   = (const float*)d_in[2];
    const float* W_rho  = (const float*)d_in[3];
    const float* U_mu   = (const float*)d_in[4];
    const float* U_rho  = (const float*)d_in[5];
    const float* b_mu   = (const float*)d_in[6];
    const float* b_rho  = (const float*)d_in[7];
    // d_in[8] = r_eps (dead)
    const float* u_eps  = (const float*)d_in[9];
    const float* h_eps  = (const float*)d_in[10];
    float* out = (float*)d_out;

    cudaFuncSetAttribute(gemm_kernel, cudaFuncAttributeMaxDynamicSharedMemorySize, SMEM_BYTES);

    build_A_kernel<<<(MDIM * 1024) / 256, 256>>>(x, h_prev);
    build_Bt_kernel<<<dim3(128, 32, 2), dim3(32, 8)>>>(W_mu, W_rho, U_mu, U_rho, u_eps, h_eps);
    build_bias_kernel<<<8, 256>>>(b_mu, b_rho, u_eps, h_eps);

    gemm_kernel<<<dim3(NDIM / BNT, MDIM / BMT), 512, SMEM_BYTES>>>(h_prev, out);
}

// round 5
// speedup vs baseline: 2.3285x; 1.0403x over previous
#include <cuda_runtime.h>
#include <cuda_bf16.h>
#include <math.h>
#include <stdint.h>

// B=2048, D=H=1024.
// Fused: A=[x, h, x^2, h^2] (2048x4096),
//        Bt[n,k], n=2*j+g interleaved (g=0:u gate, 1:h gate), from
//        [W_mu;U_mu;eps*sp2(W_rho);eps*sp2(U_rho)] columns [1024,3072).
// arg = A @ Bt^T + bias ; u=sigmoid, hp=tanh, out = u*h_prev + (1-u)*hp.
// (r gate is dead code in the reference.)
// GEMM: split-precision bf16 on mma.sync m16n8k16:
//   D = Ah*Bh + Al*Bh + Ah*Bl, fp32 accum in registers.
// R5: 128x128 tiles, 256 thr, NSTG=2 -> 2 CTAs/SM, grid 256 covers all SMs.

#define MDIM 2048
#define NDIM 2048
#define KDIM 4096
#define HDIM 1024

__device__ __align__(128) __nv_bfloat16 g_A_hi[(size_t)MDIM * KDIM];
__device__ __align__(128) __nv_bfloat16 g_A_lo[(size_t)MDIM * KDIM];
__device__ __align__(128) __nv_bfloat16 g_B_hi[(size_t)NDIM * KDIM];
__device__ __align__(128) __nv_bfloat16 g_B_lo[(size_t)NDIM * KDIM];
__device__ float g_bias[NDIM];

__device__ __forceinline__ float softplusf(float r) {
    return (r > 20.0f) ? r : log1pf(expf(r));
}

__device__ __forceinline__ void split_store(float v, __nv_bfloat16* hi, __nv_bfloat16* lo) {
    __nv_bfloat16 h = __float2bfloat16(v);
    *hi = h;
    *lo = __float2bfloat16(v - __bfloat162float(h));
}

// ---------------------------------------------------------------------------
// Preprocessing
// ---------------------------------------------------------------------------

__global__ void build_A_kernel(const float* __restrict__ x, const float* __restrict__ h) {
    int idx = blockIdx.x * 256 + threadIdx.x;   // 2048*1024
    int b = idx >> 10;
    int k = idx & 1023;
    float xv = x[idx];
    float hv = h[idx];
    size_t base = (size_t)b * KDIM;
    split_store(xv,      g_A_hi + base + k,        g_A_lo + base + k);
    split_store(hv,      g_A_hi + base + 1024 + k, g_A_lo + base + 1024 + k);
    split_store(xv * xv, g_A_hi + base + 2048 + k, g_A_lo + base + 2048 + k);
    split_store(hv * hv, g_A_hi + base + 3072 + k, g_A_lo + base + 3072 + k);
}

// Tiled transpose: Bt[n=2*jj+g, k]. grid (128, 32, 2), block (32, 8)
__global__ void build_Bt_kernel(const float* __restrict__ W_mu, const float* __restrict__ W_rho,
                                const float* __restrict__ U_mu, const float* __restrict__ U_rho,
                                const float* __restrict__ u_eps, const float* __restrict__ h_eps) {
    __shared__ float tile[32][33];
    int k0  = blockIdx.x * 32;
    int jj0 = blockIdx.y * 32;
    int g   = blockIdx.z;
    int tx = threadIdx.x, ty = threadIdx.y;
    int gcol = (g + 1) * 1024 + jj0 + tx;
#pragma unroll
    for (int i = 0; i < 4; ++i) {
        int k = k0 + ty + i * 8;
        float v;
        if (k < 1024)       v = W_mu[(size_t)k * 3072 + gcol];
        else if (k < 2048)  v = U_mu[(size_t)(k - 1024) * 3072 + gcol];
        else {
            float rho = (k < 3072) ? W_rho[(size_t)(k - 2048) * 3072 + gcol]
                                   : U_rho[(size_t)(k - 3072) * 3072 + gcol];
            float s = softplusf(rho);
            v = s * s;
        }
        tile[ty + i * 8][tx] = v;
    }
    __syncthreads();
    bool sigreg = (k0 >= 2048);
#pragma unroll
    for (int i = 0; i < 4; ++i) {
        int jj = jj0 + ty + i * 8;
        float v = tile[tx][ty + i * 8];          // source (k0+tx, jj)
        if (sigreg) v *= (g ? h_eps[jj] : u_eps[jj]);
        int n = 2 * jj + g;
        size_t off = (size_t)n * KDIM + k0 + tx;
        split_store(v, g_B_hi + off, g_B_lo + off);
    }
}

__global__ void build_bias_kernel(const float* __restrict__ b_mu, const float* __restrict__ b_rho,
                                  const float* __restrict__ u_eps, const float* __restrict__ h_eps) {
    int n = blockIdx.x * 256 + threadIdx.x;
    if (n >= NDIM) return;
    int jj = n >> 1, g = n & 1;
    int gcol = (g + 1) * 1024 + jj;
    float eps = g ? h_eps[jj] : u_eps[jj];
    g_bias[n] = b_mu[gcol] + eps * softplusf(b_rho[gcol]);
}

// ---------------------------------------------------------------------------
// GEMM: 2048x2048x4096 split-bf16 via mma.sync m16n8k16
// 128x128 tile, 256 threads, 8 warps (2 M x 4 N), warp tile 64x32
// ---------------------------------------------------------------------------

#define BMT 128
#define BNT 128
#define BKC 32
#define KT (KDIM / BKC)          // 128
#define TILE_B (128 * 80)        // one 128-row x 80B padded tile = 10240 bytes
#define AH_OFF 0
#define AL_OFF (1 * TILE_B)
#define BH_OFF (2 * TILE_B)
#define BL_OFF (3 * TILE_B)
#define STG (4 * TILE_B)         // 40960 bytes
#define NSTG 2
#define SMEM_BYTES (NSTG * STG)  // 81920 bytes -> 2 CTAs/SM

static __device__ __forceinline__ uint32_t smem_u32(const void* p) {
    uint32_t a;
    asm("{ .reg .u64 t; cvta.to.shared.u64 t, %1; cvt.u32.u64 %0, t; }" : "=r"(a) : "l"(p));
    return a;
}
static __device__ __forceinline__ void cp16(uint32_t saddr, const void* g) {
    asm volatile("cp.async.cg.shared.global [%0], [%1], 16;" :: "r"(saddr), "l"(g));
}
static __device__ __forceinline__ void cp_commit() {
    asm volatile("cp.async.commit_group;" ::: "memory");
}
template <int N> static __device__ __forceinline__ void cp_wait() {
    asm volatile("cp.async.wait_group %0;" :: "n"(N) : "memory");
}
static __device__ __forceinline__ void ldsm4(uint32_t& r0, uint32_t& r1, uint32_t& r2, uint32_t& r3,
                                             uint32_t addr) {
    asm volatile("ldmatrix.sync.aligned.m8n8.x4.shared.b16 {%0,%1,%2,%3}, [%4];"
                 : "=r"(r0), "=r"(r1), "=r"(r2), "=r"(r3) : "r"(addr));
}
static __device__ __forceinline__ void mma16816(float* c, const uint32_t* a, uint32_t b0, uint32_t b1) {
    asm volatile("mma.sync.aligned.m16n8k16.row.col.f32.bf16.bf16.f32 "
                 "{%0,%1,%2,%3}, {%4,%5,%6,%7}, {%8,%9}, {%0,%1,%2,%3};"
                 : "+f"(c[0]), "+f"(c[1]), "+f"(c[2]), "+f"(c[3])
                 : "r"(a[0]), "r"(a[1]), "r"(a[2]), "r"(a[3]), "r"(b0), "r"(b1));
}

__global__ __launch_bounds__(256, 2) void gemm_kernel(const float* __restrict__ h_prev,
                                                      float* __restrict__ out) {
    extern __shared__ char sm[];
    const uint32_t sbase = smem_u32(sm);

    const int tid  = threadIdx.x;
    const int lane = tid & 31, wid = tid >> 5;
    const int warp_m = wid & 1, warp_n = wid >> 1;   // 2 x 4 warps
    const int bm = blockIdx.y, bn = blockIdx.x;

    const char* AhG = (const char*)g_A_hi + (size_t)(bm * BMT) * (KDIM * 2);
    const char* AlG = (const char*)g_A_lo + (size_t)(bm * BMT) * (KDIM * 2);
    const char* BhG = (const char*)g_B_hi + (size_t)(bn * BNT) * (KDIM * 2);
    const char* BlG = (const char*)g_B_lo + (size_t)(bn * BNT) * (KDIM * 2);

    // cp.async mapping: 128 rows x 4 x 16B lines per tile = 512 lines; 256 thr -> 2/thread/tile
    const int lr = tid >> 2, ls = tid & 3;
    const uint32_t s_off0 = (uint32_t)(lr * 80 + ls * 16);
    const size_t   g_off0 = (size_t)lr * (KDIM * 2) + ls * 16;
    const uint32_t s_off1 = (uint32_t)((lr + 64) * 80 + ls * 16);
    const size_t   g_off1 = (size_t)(lr + 64) * (KDIM * 2) + ls * 16;

    auto load_chunk = [&](int stage, int kt) {
        const uint32_t st = sbase + stage * STG;
        const size_t kb = (size_t)kt * 64;   // 32 elems * 2B
        cp16(st + AH_OFF + s_off0, AhG + g_off0 + kb);
        cp16(st + AH_OFF + s_off1, AhG + g_off1 + kb);
        cp16(st + AL_OFF + s_off0, AlG + g_off0 + kb);
        cp16(st + AL_OFF + s_off1, AlG + g_off1 + kb);
        cp16(st + BH_OFF + s_off0, BhG + g_off0 + kb);
        cp16(st + BH_OFF + s_off1, BhG + g_off1 + kb);
        cp16(st + BL_OFF + s_off0, BlG + g_off0 + kb);
        cp16(st + BL_OFF + s_off1, BlG + g_off1 + kb);
        cp_commit();
    };

    float acc[4][4][4];
#pragma unroll
    for (int i = 0; i < 4; ++i)
#pragma unroll
        for (int j = 0; j < 4; ++j)
#pragma unroll
            for (int q = 0; q < 4; ++q) acc[i][j][q] = 0.0f;

    // ldmatrix per-lane base offsets (within a stage)
    const uint32_t aA_off = (uint32_t)((warp_m * 64 + (lane & 15)) * 80 + (lane >> 4) * 16);
    const uint32_t aB_off = (uint32_t)(BH_OFF +
                     (warp_n * 32 + ((lane >> 4) << 3) + (lane & 7)) * 80 + ((lane >> 3) & 1) * 16);

    load_chunk(0, 0);

    for (int kt = 0; kt < KT; ++kt) {
        const int stage = kt & 1;
        cp_wait<0>();
        __syncthreads();
        if (kt + 1 < KT) load_chunk(stage ^ 1, kt + 1);

        const uint32_t st = sbase + stage * STG;
        const uint32_t aAh = st + aA_off;
        const uint32_t aB  = st + aB_off;

#pragma unroll
        for (int ks = 0; ks < 2; ++ks) {
            const uint32_t ka = ks * 32;   // 16 elems * 2B
            uint32_t ah[4][4], al[4][4];
#pragma unroll
            for (int mt = 0; mt < 4; ++mt) {
                ldsm4(ah[mt][0], ah[mt][1], ah[mt][2], ah[mt][3], aAh + mt * 16 * 80 + ka);
                ldsm4(al[mt][0], al[mt][1], al[mt][2], al[mt][3],
                      aAh + (AL_OFF - AH_OFF) + mt * 16 * 80 + ka);
            }
#pragma unroll
            for (int p = 0; p < 2; ++p) {
                uint32_t bh0, bh1, bh2, bh3, bl0, bl1, bl2, bl3;
                ldsm4(bh0, bh1, bh2, bh3, aB + p * 16 * 80 + ka);
                ldsm4(bl0, bl1, bl2, bl3, aB + (BL_OFF - BH_OFF) + p * 16 * 80 + ka);
                const int nt0 = 2 * p, nt1 = 2 * p + 1;
#pragma unroll
                for (int mt = 0; mt < 4; ++mt) {
                    mma16816(acc[mt][nt0], ah[mt], bh0, bh1);
                    mma16816(acc[mt][nt1], ah[mt], bh2, bh3);
                    mma16816(acc[mt][nt0], al[mt], bh0, bh1);
                    mma16816(acc[mt][nt1], al[mt], bh2, bh3);
                    mma16816(acc[mt][nt0], ah[mt], bl0, bl1);
                    mma16816(acc[mt][nt1], ah[mt], bl2, bl3);
                }
            }
        }
    }

    // Epilogue: adjacent accumulator column pair = (u-gate, h-gate) for one j.
    const int r_base = bm * BMT + warp_m * 64 + (lane >> 2);
#pragma unroll
    for (int mt = 0; mt < 4; ++mt) {
#pragma unroll
        for (int nt = 0; nt < 4; ++nt) {
            const int n0 = bn * BNT + warp_n * 32 + nt * 8 + (lane & 3) * 2;
            const float bu = g_bias[n0];
            const float bh = g_bias[n0 + 1];
            const int j = n0 >> 1;
#pragma unroll
            for (int hlf = 0; hlf < 2; ++hlf) {
                const int row = r_base + mt * 16 + hlf * 8;
                const float au  = acc[mt][nt][hlf * 2]     + bu;
                const float ahv = acc[mt][nt][hlf * 2 + 1] + bh;
                const float u  = 1.0f / (1.0f + __expf(-au));
                const float hp = tanhf(ahv);
                const size_t g = (size_t)row * HDIM + j;
                out[g] = u * h_prev[g] + (1.0f - u) * hp;
            }
        }
    }
}

// ---------------------------------------------------------------------------
// Launch
// ---------------------------------------------------------------------------

extern "C" void kernel_launch(void* const* d_in, const int* in_sizes, int n_in,
                              void* d_out, int out_size) {
    const float* x      = (const float*)d_in[0];
    const float* h_prev = (const float*)d_in[1];
    const float* W_mu   = (const float*)d_in[2];
    const float* W_rho  = (const float*)d_in[3];
    const float* U_mu   = (const float*)d_in[4];
    const float* U_rho  = (const float*)d_in[5];
    const float* b_mu   = (const float*)d_in[6];
    const float* b_rho  = (const float*)d_in[7];
    // d_in[8] = r_eps (dead)
    const float* u_eps  = (const float*)d_in[9];
    const float* h_eps  = (const float*)d_in[10];
    float* out = (float*)d_out;

    cudaFuncSetAttribute(gemm_kernel, cudaFuncAttributeMaxDynamicSharedMemorySize, SMEM_BYTES);

    build_A_kernel<<<(MDIM * 1024) / 256, 256>>>(x, h_prev);
    build_Bt_kernel<<<dim3(128, 32, 2), dim3(32, 8)>>>(W_mu, W_rho, U_mu, U_rho, u_eps, h_eps);
    build_bias_kernel<<<8, 256>>>(b_mu, b_rho, u_eps, h_eps);

    gemm_kernel<<<dim3(NDIM / BNT, MDIM / BMT), 256, SMEM_BYTES>>>(h_prev, out);
}

// round 6
// speedup vs baseline: 2.5461x; 1.0935x over previous
#include <cuda_runtime.h>
#include <cuda_bf16.h>
#include <math.h>
#include <stdint.h>

// B=2048, D=H=1024.
// Fused: A=[x, h, x^2, h^2] (2048x4096),
//        Bt[n,k], n=2*j+g interleaved (g=0:u gate, 1:h gate), from
//        [W_mu;U_mu;eps*sp2(W_rho);eps*sp2(U_rho)] columns [1024,3072).
// arg = A @ Bt^T + bias ; u=sigmoid, hp=tanh, out = u*h_prev + (1-u)*hp.
// (r gate is dead code in the reference.)
// GEMM: split-precision bf16 on mma.sync m16n8k16:
//   D = Ah*Bh + Al*Bh + Ah*Bl, fp32 accum in registers.
// R6: 3-stage cp.async pipeline (wait<1>), XOR-swizzled smem (no pad),
//     product-major MMA order. 2 CTAs/SM.

#define MDIM 2048
#define NDIM 2048
#define KDIM 4096
#define HDIM 1024

__device__ __align__(128) __nv_bfloat16 g_A_hi[(size_t)MDIM * KDIM];
__device__ __align__(128) __nv_bfloat16 g_A_lo[(size_t)MDIM * KDIM];
__device__ __align__(128) __nv_bfloat16 g_B_hi[(size_t)NDIM * KDIM];
__device__ __align__(128) __nv_bfloat16 g_B_lo[(size_t)NDIM * KDIM];
__device__ float g_bias[NDIM];

__device__ __forceinline__ float softplusf(float r) {
    return (r > 20.0f) ? r : log1pf(expf(r));
}

__device__ __forceinline__ void split_store(float v, __nv_bfloat16* hi, __nv_bfloat16* lo) {
    __nv_bfloat16 h = __float2bfloat16(v);
    *hi = h;
    *lo = __float2bfloat16(v - __bfloat162float(h));
}

// ---------------------------------------------------------------------------
// Preprocessing
// ---------------------------------------------------------------------------

__global__ void build_A_kernel(const float* __restrict__ x, const float* __restrict__ h) {
    int idx = blockIdx.x * 256 + threadIdx.x;   // 2048*1024
    int b = idx >> 10;
    int k = idx & 1023;
    float xv = x[idx];
    float hv = h[idx];
    size_t base = (size_t)b * KDIM;
    split_store(xv,      g_A_hi + base + k,        g_A_lo + base + k);
    split_store(hv,      g_A_hi + base + 1024 + k, g_A_lo + base + 1024 + k);
    split_store(xv * xv, g_A_hi + base + 2048 + k, g_A_lo + base + 2048 + k);
    split_store(hv * hv, g_A_hi + base + 3072 + k, g_A_lo + base + 3072 + k);
}

// Tiled transpose: Bt[n=2*jj+g, k]. grid (128, 32, 2), block (32, 8)
__global__ void build_Bt_kernel(const float* __restrict__ W_mu, const float* __restrict__ W_rho,
                                const float* __restrict__ U_mu, const float* __restrict__ U_rho,
                                const float* __restrict__ u_eps, const float* __restrict__ h_eps) {
    __shared__ float tile[32][33];
    int k0  = blockIdx.x * 32;
    int jj0 = blockIdx.y * 32;
    int g   = blockIdx.z;
    int tx = threadIdx.x, ty = threadIdx.y;
    int gcol = (g + 1) * 1024 + jj0 + tx;
#pragma unroll
    for (int i = 0; i < 4; ++i) {
        int k = k0 + ty + i * 8;
        float v;
        if (k < 1024)       v = W_mu[(size_t)k * 3072 + gcol];
        else if (k < 2048)  v = U_mu[(size_t)(k - 1024) * 3072 + gcol];
        else {
            float rho = (k < 3072) ? W_rho[(size_t)(k - 2048) * 3072 + gcol]
                                   : U_rho[(size_t)(k - 3072) * 3072 + gcol];
            float s = softplusf(rho);
            v = s * s;
        }
        tile[ty + i * 8][tx] = v;
    }
    __syncthreads();
    bool sigreg = (k0 >= 2048);
#pragma unroll
    for (int i = 0; i < 4; ++i) {
        int jj = jj0 + ty + i * 8;
        float v = tile[tx][ty + i * 8];          // source (k0+tx, jj)
        if (sigreg) v *= (g ? h_eps[jj] : u_eps[jj]);
        int n = 2 * jj + g;
        size_t off = (size_t)n * KDIM + k0 + tx;
        split_store(v, g_B_hi + off, g_B_lo + off);
    }
}

__global__ void build_bias_kernel(const float* __restrict__ b_mu, const float* __restrict__ b_rho,
                                  const float* __restrict__ u_eps, const float* __restrict__ h_eps) {
    int n = blockIdx.x * 256 + threadIdx.x;
    if (n >= NDIM) return;
    int jj = n >> 1, g = n & 1;
    int gcol = (g + 1) * 1024 + jj;
    float eps = g ? h_eps[jj] : u_eps[jj];
    g_bias[n] = b_mu[gcol] + eps * softplusf(b_rho[gcol]);
}

// ---------------------------------------------------------------------------
// GEMM: 2048x2048x4096 split-bf16 via mma.sync m16n8k16
// 128x128 tile, 256 threads, 8 warps (2 M x 4 N), warp tile 64x32
// SMEM: XOR swizzle (SW64 pattern), 64B rows, no padding.
// ---------------------------------------------------------------------------

#define BMT 128
#define BNT 128
#define KT (KDIM / 32)           // 128 chunks of BK=32
#define TILE_B 8192              // 128 rows x 64B
#define AH_OFF 0
#define AL_OFF 8192
#define BH_OFF 16384
#define BL_OFF 24576
#define STG 32768
#define NSTG 3
#define SMEM_BYTES (NSTG * STG)  // 98304 -> 2 CTAs/SM (196608 < 228KB)

#define SWZ(o) ((o) ^ (((o) >> 3) & 0x30))

static __device__ __forceinline__ uint32_t smem_u32(const void* p) {
    uint32_t a;
    asm("{ .reg .u64 t; cvta.to.shared.u64 t, %1; cvt.u32.u64 %0, t; }" : "=r"(a) : "l"(p));
    return a;
}
static __device__ __forceinline__ void cp16(uint32_t saddr, const void* g) {
    asm volatile("cp.async.cg.shared.global [%0], [%1], 16;" :: "r"(saddr), "l"(g));
}
static __device__ __forceinline__ void cp_commit() {
    asm volatile("cp.async.commit_group;" ::: "memory");
}
template <int N> static __device__ __forceinline__ void cp_wait() {
    asm volatile("cp.async.wait_group %0;" :: "n"(N) : "memory");
}
static __device__ __forceinline__ void ldsm4(uint32_t& r0, uint32_t& r1, uint32_t& r2, uint32_t& r3,
                                             uint32_t addr) {
    asm volatile("ldmatrix.sync.aligned.m8n8.x4.shared.b16 {%0,%1,%2,%3}, [%4];"
                 : "=r"(r0), "=r"(r1), "=r"(r2), "=r"(r3) : "r"(addr));
}
static __device__ __forceinline__ void mma16816(float* c, const uint32_t* a, uint32_t b0, uint32_t b1) {
    asm volatile("mma.sync.aligned.m16n8k16.row.col.f32.bf16.bf16.f32 "
                 "{%0,%1,%2,%3}, {%4,%5,%6,%7}, {%8,%9}, {%0,%1,%2,%3};"
                 : "+f"(c[0]), "+f"(c[1]), "+f"(c[2]), "+f"(c[3])
                 : "r"(a[0]), "r"(a[1]), "r"(a[2]), "r"(a[3]), "r"(b0), "r"(b1));
}

__global__ __launch_bounds__(256, 2) void gemm_kernel(const float* __restrict__ h_prev,
                                                      float* __restrict__ out) {
    extern __shared__ char sm[];
    const uint32_t sbase = smem_u32(sm);

    const int tid  = threadIdx.x;
    const int lane = tid & 31, wid = tid >> 5;
    const int warp_m = wid & 1, warp_n = wid >> 1;   // 2 x 4
    const int bm = blockIdx.y, bn = blockIdx.x;

    const char* AhG = (const char*)g_A_hi + (size_t)(bm * BMT) * (KDIM * 2);
    const char* AlG = (const char*)g_A_lo + (size_t)(bm * BMT) * (KDIM * 2);
    const char* BhG = (const char*)g_B_hi + (size_t)(bn * BNT) * (KDIM * 2);
    const char* BlG = (const char*)g_B_lo + (size_t)(bn * BNT) * (KDIM * 2);

    // cp.async mapping: 512 16B lines/tile, 256 threads -> 2 lines/thread/tile
    const int L0 = tid, L1 = tid + 256;
    const int r0 = L0 >> 2, s0 = L0 & 3;
    const int r1 = L1 >> 2, s1 = L1 & 3;
    const uint32_t so0 = SWZ((uint32_t)(r0 * 64 + s0 * 16));
    const uint32_t so1 = SWZ((uint32_t)(r1 * 64 + s1 * 16));
    const size_t go0 = (size_t)r0 * (KDIM * 2) + s0 * 16;
    const size_t go1 = (size_t)r1 * (KDIM * 2) + s1 * 16;

    auto load_chunk = [&](int stage, int kt) {
        const uint32_t st = sbase + stage * STG;
        const size_t kb = (size_t)kt * 64;
        cp16(st + AH_OFF + so0, AhG + go0 + kb);
        cp16(st + AH_OFF + so1, AhG + go1 + kb);
        cp16(st + AL_OFF + so0, AlG + go0 + kb);
        cp16(st + AL_OFF + so1, AlG + go1 + kb);
        cp16(st + BH_OFF + so0, BhG + go0 + kb);
        cp16(st + BH_OFF + so1, BhG + go1 + kb);
        cp16(st + BL_OFF + so0, BlG + go0 + kb);
        cp16(st + BL_OFF + so1, BlG + go1 + kb);
        cp_commit();
    };

    float acc[4][4][4];
#pragma unroll
    for (int i = 0; i < 4; ++i)
#pragma unroll
        for (int j = 0; j < 4; ++j)
#pragma unroll
            for (int q = 0; q < 4; ++q) acc[i][j][q] = 0.0f;

    // ldmatrix unswizzled base offsets; xor mask = (lane&6)<<3 (applied post-add)
    const uint32_t xmask = (uint32_t)((lane & 6) << 3);
    const uint32_t aBase = (uint32_t)((warp_m * 64 + (lane & 15)) * 64 + (lane >> 4) * 16);
    const uint32_t bBase = (uint32_t)((warp_n * 32 + ((lane >> 4) << 3) + (lane & 7)) * 64 +
                                      ((lane >> 3) & 1) * 16);

    load_chunk(0, 0);
    load_chunk(1, 1);

    for (int kt = 0; kt < KT; ++kt) {
        const int stage = kt % NSTG;
        if (kt >= KT - 1) cp_wait<0>(); else cp_wait<1>();
        __syncthreads();
        if (kt + 2 < KT) load_chunk((kt + 2) % NSTG, kt + 2);

        const uint32_t st = sbase + stage * STG;

#pragma unroll
        for (int ks = 0; ks < 2; ++ks) {
            const uint32_t ka = ks * 32;
            uint32_t ah[4][4], al[4][4];
            uint32_t bh[2][4], bl[2][4];
#pragma unroll
            for (int p = 0; p < 2; ++p) {
                const uint32_t bo = bBase + p * 1024 + ka;
                ldsm4(bh[p][0], bh[p][1], bh[p][2], bh[p][3], st + BH_OFF + (bo ^ xmask));
                ldsm4(bl[p][0], bl[p][1], bl[p][2], bl[p][3], st + BL_OFF + (bo ^ xmask));
            }
#pragma unroll
            for (int mt = 0; mt < 4; ++mt) {
                const uint32_t ao = aBase + mt * 1024 + ka;
                ldsm4(ah[mt][0], ah[mt][1], ah[mt][2], ah[mt][3], st + AH_OFF + (ao ^ xmask));
                ldsm4(al[mt][0], al[mt][1], al[mt][2], al[mt][3], st + AL_OFF + (ao ^ xmask));
            }
            // product-major: dependent writes to same acc are 16 MMAs apart
#pragma unroll
            for (int mt = 0; mt < 4; ++mt)
#pragma unroll
                for (int p = 0; p < 2; ++p) {
                    mma16816(acc[mt][2 * p],     ah[mt], bh[p][0], bh[p][1]);
                    mma16816(acc[mt][2 * p + 1], ah[mt], bh[p][2], bh[p][3]);
                }
#pragma unroll
            for (int mt = 0; mt < 4; ++mt)
#pragma unroll
                for (int p = 0; p < 2; ++p) {
                    mma16816(acc[mt][2 * p],     al[mt], bh[p][0], bh[p][1]);
                    mma16816(acc[mt][2 * p + 1], al[mt], bh[p][2], bh[p][3]);
                }
#pragma unroll
            for (int mt = 0; mt < 4; ++mt)
#pragma unroll
                for (int p = 0; p < 2; ++p) {
                    mma16816(acc[mt][2 * p],     ah[mt], bl[p][0], bl[p][1]);
                    mma16816(acc[mt][2 * p + 1], ah[mt], bl[p][2], bl[p][3]);
                }
        }
    }

    // Epilogue: adjacent accumulator column pair = (u-gate, h-gate) for one j.
    const int r_base = bm * BMT + warp_m * 64 + (lane >> 2);
#pragma unroll
    for (int mt = 0; mt < 4; ++mt) {
#pragma unroll
        for (int nt = 0; nt < 4; ++nt) {
            const int n0 = bn * BNT + warp_n * 32 + nt * 8 + (lane & 3) * 2;
            const float bu = g_bias[n0];
            const float bh = g_bias[n0 + 1];
            const int j = n0 >> 1;
#pragma unroll
            for (int hlf = 0; hlf < 2; ++hlf) {
                const int row = r_base + mt * 16 + hlf * 8;
                const float au  = acc[mt][nt][hlf * 2]     + bu;
                const float ahv = acc[mt][nt][hlf * 2 + 1] + bh;
                const float u  = 1.0f / (1.0f + __expf(-au));
                const float hp = tanhf(ahv);
                const size_t g = (size_t)row * HDIM + j;
                out[g] = u * h_prev[g] + (1.0f - u) * hp;
            }
        }
    }
}

// ---------------------------------------------------------------------------
// Launch
// ---------------------------------------------------------------------------

extern "C" void kernel_launch(void* const* d_in, const int* in_sizes, int n_in,
                              void* d_out, int out_size) {
    const float* x      = (const float*)d_in[0];
    const float* h_prev = (const float*)d_in[1];
    const float* W_mu   = (const float*)d_in[2];
    const float* W_rho  = (const float*)d_in[3];
    const float* U_mu   = (const float*)d_in[4];
    const float* U_rho  = (const float*)d_in[5];
    const float* b_mu   = (const float*)d_in[6];
    const float* b_rho  = (const float*)d_in[7];
    // d_in[8] = r_eps (dead)
    const float* u_eps  = (const float*)d_in[9];
    const float* h_eps  = (const float*)d_in[10];
    float* out = (float*)d_out;

    cudaFuncSetAttribute(gemm_kernel, cudaFuncAttributeMaxDynamicSharedMemorySize, SMEM_BYTES);

    build_A_kernel<<<(MDIM * 1024) / 256, 256>>>(x, h_prev);
    build_Bt_kernel<<<dim3(128, 32, 2), dim3(32, 8)>>>(W_mu, W_rho, U_mu, U_rho, u_eps, h_eps);
    build_bias_kernel<<<8, 256>>>(b_mu, b_rho, u_eps, h_eps);

    gemm_kernel<<<dim3(NDIM / BNT, MDIM / BMT), 256, SMEM_BYTES>>>(h_prev, out);
}

// round 7
// speedup vs baseline: 3.2796x; 1.2881x over previous
#include <cuda_runtime.h>
#include <cuda_bf16.h>
#include <math.h>
#include <stdint.h>

// B=2048, D=H=1024.
// Fused: A=[x, h, x^2, h^2] (2048x4096),
//        Bt[n,k], n=2*j+g interleaved (g=0:u gate, 1:h gate), from
//        [W_mu;U_mu;eps*sp2(W_rho);eps*sp2(U_rho)] columns [1024,3072).
// arg = A @ Bt^T + bias ; u=sigmoid, hp=tanh, out = u*h_prev + (1-u)*hp.
// (r gate is dead code in the reference.)
// GEMM: precision-differentiated split bf16 on mma.sync m16n8k16:
//   mu half  (K in [0,2048)):   D += Ah*Bh + Al*Bh + Ah*Bl  (3 products)
//   sig half (K in [2048,4096)): D += Ah*Bh                  (1 product;
//     sig weights ~3e-4 -> bf16 quantization error ~5e-5 abs, 10x margin)

#define MDIM 2048
#define NDIM 2048
#define KDIM 4096
#define HDIM 1024

__device__ __align__(128) __nv_bfloat16 g_A_hi[(size_t)MDIM * KDIM];
__device__ __align__(128) __nv_bfloat16 g_A_lo[(size_t)MDIM * KDIM];
__device__ __align__(128) __nv_bfloat16 g_B_hi[(size_t)NDIM * KDIM];
__device__ __align__(128) __nv_bfloat16 g_B_lo[(size_t)NDIM * KDIM];
__device__ float g_bias[NDIM];

__device__ __forceinline__ float softplusf(float r) {
    return (r > 20.0f) ? r : log1pf(expf(r));
}

__device__ __forceinline__ void split_store(float v, __nv_bfloat16* hi, __nv_bfloat16* lo) {
    __nv_bfloat16 h = __float2bfloat16(v);
    *hi = h;
    *lo = __float2bfloat16(v - __bfloat162float(h));
}

// ---------------------------------------------------------------------------
// Preprocessing
// ---------------------------------------------------------------------------

__global__ void build_A_kernel(const float* __restrict__ x, const float* __restrict__ h) {
    int idx = blockIdx.x * 256 + threadIdx.x;   // 2048*1024
    int b = idx >> 10;
    int k = idx & 1023;
    float xv = x[idx];
    float hv = h[idx];
    size_t base = (size_t)b * KDIM;
    split_store(xv, g_A_hi + base + k,        g_A_lo + base + k);
    split_store(hv, g_A_hi + base + 1024 + k, g_A_lo + base + 1024 + k);
    // sig half: hi only (single-product precision is sufficient)
    g_A_hi[base + 2048 + k] = __float2bfloat16(xv * xv);
    g_A_hi[base + 3072 + k] = __float2bfloat16(hv * hv);
}

// Tiled transpose: Bt[n=2*jj+g, k]. grid (128, 32, 2), block (32, 8)
__global__ void build_Bt_kernel(const float* __restrict__ W_mu, const float* __restrict__ W_rho,
                                const float* __restrict__ U_mu, const float* __restrict__ U_rho,
                                const float* __restrict__ u_eps, const float* __restrict__ h_eps) {
    __shared__ float tile[32][33];
    int k0  = blockIdx.x * 32;
    int jj0 = blockIdx.y * 32;
    int g   = blockIdx.z;
    int tx = threadIdx.x, ty = threadIdx.y;
    int gcol = (g + 1) * 1024 + jj0 + tx;
#pragma unroll
    for (int i = 0; i < 4; ++i) {
        int k = k0 + ty + i * 8;
        float v;
        if (k < 1024)       v = W_mu[(size_t)k * 3072 + gcol];
        else if (k < 2048)  v = U_mu[(size_t)(k - 1024) * 3072 + gcol];
        else {
            float rho = (k < 3072) ? W_rho[(size_t)(k - 2048) * 3072 + gcol]
                                   : U_rho[(size_t)(k - 3072) * 3072 + gcol];
            float s = softplusf(rho);
            v = s * s;
        }
        tile[ty + i * 8][tx] = v;
    }
    __syncthreads();
    bool sigreg = (k0 >= 2048);
#pragma unroll
    for (int i = 0; i < 4; ++i) {
        int jj = jj0 + ty + i * 8;
        float v = tile[tx][ty + i * 8];          // source (k0+tx, jj)
        int n = 2 * jj + g;
        size_t off = (size_t)n * KDIM + k0 + tx;
        if (sigreg) {
            v *= (g ? h_eps[jj] : u_eps[jj]);
            g_B_hi[off] = __float2bfloat16(v);   // hi only
        } else {
            split_store(v, g_B_hi + off, g_B_lo + off);
        }
    }
}

__global__ void build_bias_kernel(const float* __restrict__ b_mu, const float* __restrict__ b_rho,
                                  const float* __restrict__ u_eps, const float* __restrict__ h_eps) {
    int n = blockIdx.x * 256 + threadIdx.x;
    if (n >= NDIM) return;
    int jj = n >> 1, g = n & 1;
    int gcol = (g + 1) * 1024 + jj;
    float eps = g ? h_eps[jj] : u_eps[jj];
    g_bias[n] = b_mu[gcol] + eps * softplusf(b_rho[gcol]);
}

// ---------------------------------------------------------------------------
// GEMM: 2048x2048x4096 via mma.sync m16n8k16
// 128x128 tile, 256 threads, 8 warps (2 M x 4 N), warp tile 64x32
// SMEM: XOR swizzle, 64B rows, no padding. 3-stage cp.async, 2 CTAs/SM.
// ---------------------------------------------------------------------------

#define BMT 128
#define BNT 128
#define KT (KDIM / 32)           // 128 chunks of BK=32
#define KT_MU 64                 // chunks [0,64): mu (3 products); [64,128): sig (1 product)
#define TILE_B 8192              // 128 rows x 64B
#define AH_OFF 0
#define AL_OFF 8192
#define BH_OFF 16384
#define BL_OFF 24576
#define STG 32768
#define NSTG 3
#define SMEM_BYTES (NSTG * STG)  // 98304 -> 2 CTAs/SM

#define SWZ(o) ((o) ^ (((o) >> 3) & 0x30))

static __device__ __forceinline__ uint32_t smem_u32(const void* p) {
    uint32_t a;
    asm("{ .reg .u64 t; cvta.to.shared.u64 t, %1; cvt.u32.u64 %0, t; }" : "=r"(a) : "l"(p));
    return a;
}
static __device__ __forceinline__ void cp16(uint32_t saddr, const void* g) {
    asm volatile("cp.async.cg.shared.global [%0], [%1], 16;" :: "r"(saddr), "l"(g));
}
static __device__ __forceinline__ void cp_commit() {
    asm volatile("cp.async.commit_group;" ::: "memory");
}
template <int N> static __device__ __forceinline__ void cp_wait() {
    asm volatile("cp.async.wait_group %0;" :: "n"(N) : "memory");
}
static __device__ __forceinline__ void ldsm4(uint32_t& r0, uint32_t& r1, uint32_t& r2, uint32_t& r3,
                                             uint32_t addr) {
    asm volatile("ldmatrix.sync.aligned.m8n8.x4.shared.b16 {%0,%1,%2,%3}, [%4];"
                 : "=r"(r0), "=r"(r1), "=r"(r2), "=r"(r3) : "r"(addr));
}
static __device__ __forceinline__ void mma16816(float* c, const uint32_t* a, uint32_t b0, uint32_t b1) {
    asm volatile("mma.sync.aligned.m16n8k16.row.col.f32.bf16.bf16.f32 "
                 "{%0,%1,%2,%3}, {%4,%5,%6,%7}, {%8,%9}, {%0,%1,%2,%3};"
                 : "+f"(c[0]), "+f"(c[1]), "+f"(c[2]), "+f"(c[3])
                 : "r"(a[0]), "r"(a[1]), "r"(a[2]), "r"(a[3]), "r"(b0), "r"(b1));
}

__global__ __launch_bounds__(256, 2) void gemm_kernel(const float* __restrict__ h_prev,
                                                      float* __restrict__ out) {
    extern __shared__ char sm[];
    const uint32_t sbase = smem_u32(sm);

    const int tid  = threadIdx.x;
    const int lane = tid & 31, wid = tid >> 5;
    const int warp_m = wid & 1, warp_n = wid >> 1;   // 2 x 4
    const int bm = blockIdx.y, bn = blockIdx.x;

    const char* AhG = (const char*)g_A_hi + (size_t)(bm * BMT) * (KDIM * 2);
    const char* AlG = (const char*)g_A_lo + (size_t)(bm * BMT) * (KDIM * 2);
    const char* BhG = (const char*)g_B_hi + (size_t)(bn * BNT) * (KDIM * 2);
    const char* BlG = (const char*)g_B_lo + (size_t)(bn * BNT) * (KDIM * 2);

    // cp.async mapping: 512 16B lines/tile, 256 threads -> 2 lines/thread/tile
    const int L0 = tid, L1 = tid + 256;
    const int r0 = L0 >> 2, s0 = L0 & 3;
    const int r1 = L1 >> 2, s1 = L1 & 3;
    const uint32_t so0 = SWZ((uint32_t)(r0 * 64 + s0 * 16));
    const uint32_t so1 = SWZ((uint32_t)(r1 * 64 + s1 * 16));
    const size_t go0 = (size_t)r0 * (KDIM * 2) + s0 * 16;
    const size_t go1 = (size_t)r1 * (KDIM * 2) + s1 * 16;

    auto load_chunk = [&](int stage, int kt) {
        const uint32_t st = sbase + stage * STG;
        const size_t kb = (size_t)kt * 64;
        cp16(st + AH_OFF + so0, AhG + go0 + kb);
        cp16(st + AH_OFF + so1, AhG + go1 + kb);
        cp16(st + BH_OFF + so0, BhG + go0 + kb);
        cp16(st + BH_OFF + so1, BhG + go1 + kb);
        if (kt < KT_MU) {
            cp16(st + AL_OFF + so0, AlG + go0 + kb);
            cp16(st + AL_OFF + so1, AlG + go1 + kb);
            cp16(st + BL_OFF + so0, BlG + go0 + kb);
            cp16(st + BL_OFF + so1, BlG + go1 + kb);
        }
        cp_commit();
    };

    float acc[4][4][4];
#pragma unroll
    for (int i = 0; i < 4; ++i)
#pragma unroll
        for (int j = 0; j < 4; ++j)
#pragma unroll
            for (int q = 0; q < 4; ++q) acc[i][j][q] = 0.0f;

    // ldmatrix unswizzled base offsets; xor mask = (lane&6)<<3
    const uint32_t xmask = (uint32_t)((lane & 6) << 3);
    const uint32_t aBase = (uint32_t)((warp_m * 64 + (lane & 15)) * 64 + (lane >> 4) * 16);
    const uint32_t bBase = (uint32_t)((warp_n * 32 + ((lane >> 4) << 3) + (lane & 7)) * 64 +
                                      ((lane >> 3) & 1) * 16);

    load_chunk(0, 0);
    load_chunk(1, 1);

    for (int kt = 0; kt < KT; ++kt) {
        const int stage = kt % NSTG;
        if (kt >= KT - 1) cp_wait<0>(); else cp_wait<1>();
        __syncthreads();
        if (kt + 2 < KT) load_chunk((kt + 2) % NSTG, kt + 2);

        const uint32_t st = sbase + stage * STG;

        if (kt < KT_MU) {
            // mu phase: 3 products
#pragma unroll
            for (int ks = 0; ks < 2; ++ks) {
                const uint32_t ka = ks * 32;
                uint32_t ah[4][4], al[4][4];
                uint32_t bh[2][4], bl[2][4];
#pragma unroll
                for (int p = 0; p < 2; ++p) {
                    const uint32_t bo = bBase + p * 1024 + ka;
                    ldsm4(bh[p][0], bh[p][1], bh[p][2], bh[p][3], st + BH_OFF + (bo ^ xmask));
                    ldsm4(bl[p][0], bl[p][1], bl[p][2], bl[p][3], st + BL_OFF + (bo ^ xmask));
                }
#pragma unroll
                for (int mt = 0; mt < 4; ++mt) {
                    const uint32_t ao = aBase + mt * 1024 + ka;
                    ldsm4(ah[mt][0], ah[mt][1], ah[mt][2], ah[mt][3], st + AH_OFF + (ao ^ xmask));
                    ldsm4(al[mt][0], al[mt][1], al[mt][2], al[mt][3], st + AL_OFF + (ao ^ xmask));
                }
                // product-major: dependent writes to same acc are 16 MMAs apart
#pragma unroll
                for (int mt = 0; mt < 4; ++mt)
#pragma unroll
                    for (int p = 0; p < 2; ++p) {
                        mma16816(acc[mt][2 * p],     ah[mt], bh[p][0], bh[p][1]);
                        mma16816(acc[mt][2 * p + 1], ah[mt], bh[p][2], bh[p][3]);
                    }
#pragma unroll
                for (int mt = 0; mt < 4; ++mt)
#pragma unroll
                    for (int p = 0; p < 2; ++p) {
                        mma16816(acc[mt][2 * p],     al[mt], bh[p][0], bh[p][1]);
                        mma16816(acc[mt][2 * p + 1], al[mt], bh[p][2], bh[p][3]);
                    }
#pragma unroll
                for (int mt = 0; mt < 4; ++mt)
#pragma unroll
                    for (int p = 0; p < 2; ++p) {
                        mma16816(acc[mt][2 * p],     ah[mt], bl[p][0], bl[p][1]);
                        mma16816(acc[mt][2 * p + 1], ah[mt], bl[p][2], bl[p][3]);
                    }
            }
        } else {
            // sig phase: single product (hi*hi)
#pragma unroll
            for (int ks = 0; ks < 2; ++ks) {
                const uint32_t ka = ks * 32;
                uint32_t ah[4][4];
                uint32_t bh[2][4];
#pragma unroll
                for (int p = 0; p < 2; ++p) {
                    const uint32_t bo = bBase + p * 1024 + ka;
                    ldsm4(bh[p][0], bh[p][1], bh[p][2], bh[p][3], st + BH_OFF + (bo ^ xmask));
                }
#pragma unroll
                for (int mt = 0; mt < 4; ++mt) {
                    const uint32_t ao = aBase + mt * 1024 + ka;
                    ldsm4(ah[mt][0], ah[mt][1], ah[mt][2], ah[mt][3], st + AH_OFF + (ao ^ xmask));
                }
#pragma unroll
                for (int mt = 0; mt < 4; ++mt)
#pragma unroll
                    for (int p = 0; p < 2; ++p) {
                        mma16816(acc[mt][2 * p],     ah[mt], bh[p][0], bh[p][1]);
                        mma16816(acc[mt][2 * p + 1], ah[mt], bh[p][2], bh[p][3]);
                    }
            }
        }
    }

    // Epilogue: adjacent accumulator column pair = (u-gate, h-gate) for one j.
    const int r_base = bm * BMT + warp_m * 64 + (lane >> 2);
#pragma unroll
    for (int mt = 0; mt < 4; ++mt) {
#pragma unroll
        for (int nt = 0; nt < 4; ++nt) {
            const int n0 = bn * BNT + warp_n * 32 + nt * 8 + (lane & 3) * 2;
            const float bu = g_bias[n0];
            const float bh = g_bias[n0 + 1];
            const int j = n0 >> 1;
#pragma unroll
            for (int hlf = 0; hlf < 2; ++hlf) {
                const int row = r_base + mt * 16 + hlf * 8;
                const float au  = acc[mt][nt][hlf * 2]     + bu;
                const float ahv = acc[mt][nt][hlf * 2 + 1] + bh;
                const float u  = 1.0f / (1.0f + __expf(-au));
                const float hp = tanhf(ahv);
                const size_t g = (size_t)row * HDIM + j;
                out[g] = u * h_prev[g] + (1.0f - u) * hp;
            }
        }
    }
}

// ---------------------------------------------------------------------------
// Launch
// ---------------------------------------------------------------------------

extern "C" void kernel_launch(void* const* d_in, const int* in_sizes, int n_in,
                              void* d_out, int out_size) {
    const float* x      = (const float*)d_in[0];
    const float* h_prev = (const float*)d_in[1];
    const float* W_mu   = (const float*)d_in[2];
    const float* W_rho  = (const float*)d_in[3];
    const float* U_mu   = (const float*)d_in[4];
    const float* U_rho  = (const float*)d_in[5];
    const float* b_mu   = (const float*)d_in[6];
    const float* b_rho  = (const float*)d_in[7];
    // d_in[8] = r_eps (dead)
    const float* u_eps  = (const float*)d_in[9];
    const float* h_eps  = (const float*)d_in[10];
    float* out = (float*)d_out;

    cudaFuncSetAttribute(gemm_kernel, cudaFuncAttributeMaxDynamicSharedMemorySize, SMEM_BYTES);

    build_A_kernel<<<(MDIM * 1024) / 256, 256>>>(x, h_prev);
    build_Bt_kernel<<<dim3(128, 32, 2), dim3(32, 8)>>>(W_mu, W_rho, U_mu, U_rho, u_eps, h_eps);
    build_bias_kernel<<<8, 256>>>(b_mu, b_rho, u_eps, h_eps);

    gemm_kernel<<<dim3(NDIM / BNT, MDIM / BMT), 256, SMEM_BYTES>>>(h_prev, out);
}

// round 8
// speedup vs baseline: 5.8752x; 1.7914x over previous
#include <cuda_runtime.h>
#include <cuda_fp16.h>
#include <math.h>
#include <stdint.h>

// B=2048, D=H=1024.
// Fused: A=[x, h, x^2, h^2] (2048x4096) fp16,
//        Bt[n,k], n=2*j+g interleaved (g=0:u gate, 1:h gate), fp16, from
//        [W_mu;U_mu;eps*sp2(W_rho);eps*sp2(U_rho)] columns [1024,3072).
// arg = A @ Bt^T + bias ; u=sigmoid, hp=tanh, out = u*h_prev + (1-u)*hp.
// (r gate is dead code in the reference.)
// GEMM: single-product fp16 mma.sync m16n8k16 (fp32 accum). fp16's 11-bit
// mantissa gives arg error ~9e-4 abs -> output rel_err ~4e-4 < 1e-3.

#define MDIM 2048
#define NDIM 2048
#define KDIM 4096
#define HDIM 1024

__device__ __align__(128) __half g_A[(size_t)MDIM * KDIM];
__device__ __align__(128) __half g_B[(size_t)NDIM * KDIM];
__device__ float g_bias[NDIM];

__device__ __forceinline__ float softplusf(float r) {
    return (r > 20.0f) ? r : log1pf(expf(r));
}

// ---------------------------------------------------------------------------
// Preprocessing
// ---------------------------------------------------------------------------

__global__ void build_A_kernel(const float* __restrict__ x, const float* __restrict__ h) {
    int idx = blockIdx.x * 256 + threadIdx.x;   // 2048*1024
    int b = idx >> 10;
    int k = idx & 1023;
    float xv = x[idx];
    float hv = h[idx];
    size_t base = (size_t)b * KDIM;
    g_A[base + k]        = __float2half(xv);
    g_A[base + 1024 + k] = __float2half(hv);
    g_A[base + 2048 + k] = __float2half(xv * xv);
    g_A[base + 3072 + k] = __float2half(hv * hv);
}

// Tiled transpose: Bt[n=2*jj+g, k]. grid (128, 32, 2), block (32, 8)
__global__ void build_Bt_kernel(const float* __restrict__ W_mu, const float* __restrict__ W_rho,
                                const float* __restrict__ U_mu, const float* __restrict__ U_rho,
                                const float* __restrict__ u_eps, const float* __restrict__ h_eps) {
    __shared__ float tile[32][33];
    int k0  = blockIdx.x * 32;
    int jj0 = blockIdx.y * 32;
    int g   = blockIdx.z;
    int tx = threadIdx.x, ty = threadIdx.y;
    int gcol = (g + 1) * 1024 + jj0 + tx;
#pragma unroll
    for (int i = 0; i < 4; ++i) {
        int k = k0 + ty + i * 8;
        float v;
        if (k < 1024)       v = W_mu[(size_t)k * 3072 + gcol];
        else if (k < 2048)  v = U_mu[(size_t)(k - 1024) * 3072 + gcol];
        else {
            float rho = (k < 3072) ? W_rho[(size_t)(k - 2048) * 3072 + gcol]
                                   : U_rho[(size_t)(k - 3072) * 3072 + gcol];
            float s = softplusf(rho);
            v = s * s;
        }
        tile[ty + i * 8][tx] = v;
    }
    __syncthreads();
    bool sigreg = (k0 >= 2048);
#pragma unroll
    for (int i = 0; i < 4; ++i) {
        int jj = jj0 + ty + i * 8;
        float v = tile[tx][ty + i * 8];          // source (k0+tx, jj)
        if (sigreg) v *= (g ? h_eps[jj] : u_eps[jj]);
        int n = 2 * jj + g;
        g_B[(size_t)n * KDIM + k0 + tx] = __float2half(v);
    }
}

__global__ void build_bias_kernel(const float* __restrict__ b_mu, const float* __restrict__ b_rho,
                                  const float* __restrict__ u_eps, const float* __restrict__ h_eps) {
    int n = blockIdx.x * 256 + threadIdx.x;
    if (n >= NDIM) return;
    int jj = n >> 1, g = n & 1;
    int gcol = (g + 1) * 1024 + jj;
    float eps = g ? h_eps[jj] : u_eps[jj];
    g_bias[n] = b_mu[gcol] + eps * softplusf(b_rho[gcol]);
}

// ---------------------------------------------------------------------------
// GEMM: 2048x2048x4096 fp16 via mma.sync m16n8k16, fp32 accum
// 128x128 tile, 256 threads, 8 warps (2 M x 4 N), warp tile 64x32
// BK=64: 64 iterations. SMEM: SW128 swizzle, 128B rows. 3 stages, 2 CTAs/SM.
// ---------------------------------------------------------------------------

#define BMT 128
#define BNT 128
#define KT (KDIM / 64)           // 64 chunks of BK=64
#define TILE_B 16384             // 128 rows x 128B
#define A_OFF 0
#define B_OFF 16384
#define STG 32768
#define NSTG 3
#define SMEM_BYTES (NSTG * STG)  // 98304 -> 2 CTAs/SM

static __device__ __forceinline__ uint32_t smem_u32(const void* p) {
    uint32_t a;
    asm("{ .reg .u64 t; cvta.to.shared.u64 t, %1; cvt.u32.u64 %0, t; }" : "=r"(a) : "l"(p));
    return a;
}
static __device__ __forceinline__ void cp16(uint32_t saddr, const void* g) {
    asm volatile("cp.async.cg.shared.global [%0], [%1], 16;" :: "r"(saddr), "l"(g));
}
static __device__ __forceinline__ void cp_commit() {
    asm volatile("cp.async.commit_group;" ::: "memory");
}
template <int N> static __device__ __forceinline__ void cp_wait() {
    asm volatile("cp.async.wait_group %0;" :: "n"(N) : "memory");
}
static __device__ __forceinline__ void ldsm4(uint32_t& r0, uint32_t& r1, uint32_t& r2, uint32_t& r3,
                                             uint32_t addr) {
    asm volatile("ldmatrix.sync.aligned.m8n8.x4.shared.b16 {%0,%1,%2,%3}, [%4];"
                 : "=r"(r0), "=r"(r1), "=r"(r2), "=r"(r3) : "r"(addr));
}
static __device__ __forceinline__ void mma16816(float* c, const uint32_t* a, uint32_t b0, uint32_t b1) {
    asm volatile("mma.sync.aligned.m16n8k16.row.col.f32.f16.f16.f32 "
                 "{%0,%1,%2,%3}, {%4,%5,%6,%7}, {%8,%9}, {%0,%1,%2,%3};"
                 : "+f"(c[0]), "+f"(c[1]), "+f"(c[2]), "+f"(c[3])
                 : "r"(a[0]), "r"(a[1]), "r"(a[2]), "r"(a[3]), "r"(b0), "r"(b1));
}

__global__ __launch_bounds__(256, 2) void gemm_kernel(const float* __restrict__ h_prev,
                                                      float* __restrict__ out) {
    extern __shared__ char sm[];
    const uint32_t sbase = smem_u32(sm);

    const int tid  = threadIdx.x;
    const int lane = tid & 31, wid = tid >> 5;
    const int warp_m = wid & 1, warp_n = wid >> 1;   // 2 x 4
    const int bm = blockIdx.y, bn = blockIdx.x;

    const char* AG = (const char*)g_A + (size_t)(bm * BMT) * (KDIM * 2);
    const char* BG = (const char*)g_B + (size_t)(bn * BNT) * (KDIM * 2);

    // cp.async mapping: per tile 1024 16B lines (128 rows x 8 segs);
    // 256 threads -> 4 lines/thread/tile. SW128: seg phase ^= (row&7).
    uint32_t soff[4];
    size_t   goff[4];
#pragma unroll
    for (int i = 0; i < 4; ++i) {
        int L = tid + i * 256;
        int row = L >> 3, seg = L & 7;
        soff[i] = (uint32_t)(row * 128 + ((seg * 16) ^ ((row & 7) << 4)));
        goff[i] = (size_t)row * (KDIM * 2) + seg * 16;
    }

    auto load_chunk = [&](int stage, int kt) {
        const uint32_t st = sbase + stage * STG;
        const size_t kb = (size_t)kt * 128;   // 64 elems * 2B
#pragma unroll
        for (int i = 0; i < 4; ++i) {
            cp16(st + A_OFF + soff[i], AG + goff[i] + kb);
            cp16(st + B_OFF + soff[i], BG + goff[i] + kb);
        }
        cp_commit();
    };

    float acc[4][4][4];
#pragma unroll
    for (int i = 0; i < 4; ++i)
#pragma unroll
        for (int j = 0; j < 4; ++j)
#pragma unroll
            for (int q = 0; q < 4; ++q) acc[i][j][q] = 0.0f;

    // ldmatrix bases: row*128 aligned, xor mask = (row&7)<<4 applied to koff
    const int arow_l = lane & 15;              // row within 16-row block
    const uint32_t a_k0 = (uint32_t)((lane >> 4) * 16);
    const int brow_l = ((lane >> 4) << 3) + (lane & 7);
    const uint32_t b_k0 = (uint32_t)(((lane >> 3) & 1) * 16);

    load_chunk(0, 0);
    load_chunk(1, 1);

    for (int kt = 0; kt < KT; ++kt) {
        const int stage = kt % NSTG;
        if (kt >= KT - 1) cp_wait<0>(); else cp_wait<1>();
        __syncthreads();
        if (kt + 2 < KT) load_chunk((kt + 2) % NSTG, kt + 2);

        const uint32_t st = sbase + stage * STG;

#pragma unroll
        for (int ks = 0; ks < 4; ++ks) {
            const uint32_t ka = ks * 32;
            uint32_t af[4][4];
            uint32_t bf[2][4];
#pragma unroll
            for (int p = 0; p < 2; ++p) {
                const int row = warp_n * 32 + p * 16 + brow_l;
                const uint32_t koff = (b_k0 + ka) ^ ((uint32_t)(row & 7) << 4);
                ldsm4(bf[p][0], bf[p][1], bf[p][2], bf[p][3],
                      st + B_OFF + (uint32_t)row * 128 + koff);
            }
#pragma unroll
            for (int mt = 0; mt < 4; ++mt) {
                const int row = warp_m * 64 + mt * 16 + arow_l;
                const uint32_t koff = (a_k0 + ka) ^ ((uint32_t)(row & 7) << 4);
                ldsm4(af[mt][0], af[mt][1], af[mt][2], af[mt][3],
                      st + A_OFF + (uint32_t)row * 128 + koff);
            }
#pragma unroll
            for (int mt = 0; mt < 4; ++mt)
#pragma unroll
                for (int p = 0; p < 2; ++p) {
                    mma16816(acc[mt][2 * p],     af[mt], bf[p][0], bf[p][1]);
                    mma16816(acc[mt][2 * p + 1], af[mt], bf[p][2], bf[p][3]);
                }
        }
    }

    // Epilogue: adjacent accumulator column pair = (u-gate, h-gate) for one j.
    const int r_base = bm * BMT + warp_m * 64 + (lane >> 2);
#pragma unroll
    for (int mt = 0; mt < 4; ++mt) {
#pragma unroll
        for (int nt = 0; nt < 4; ++nt) {
            const int n0 = bn * BNT + warp_n * 32 + nt * 8 + (lane & 3) * 2;
            const float bu = g_bias[n0];
            const float bh = g_bias[n0 + 1];
            const int j = n0 >> 1;
#pragma unroll
            for (int hlf = 0; hlf < 2; ++hlf) {
                const int row = r_base + mt * 16 + hlf * 8;
                const float au  = acc[mt][nt][hlf * 2]     + bu;
                const float ahv = acc[mt][nt][hlf * 2 + 1] + bh;
                const float u  = 1.0f / (1.0f + __expf(-au));
                const float hp = tanhf(ahv);
                const size_t g = (size_t)row * HDIM + j;
                out[g] = u * h_prev[g] + (1.0f - u) * hp;
            }
        }
    }
}

// ---------------------------------------------------------------------------
// Launch
// ---------------------------------------------------------------------------

extern "C" void kernel_launch(void* const* d_in, const int* in_sizes, int n_in,
                              void* d_out, int out_size) {
    const float* x      = (const float*)d_in[0];
    const float* h_prev = (const float*)d_in[1];
    const float* W_mu   = (const float*)d_in[2];
    const float* W_rho  = (const float*)d_in[3];
    const float* U_mu   = (const float*)d_in[4];
    const float* U_rho  = (const float*)d_in[5];
    const float* b_mu   = (const float*)d_in[6];
    const float* b_rho  = (const float*)d_in[7];
    // d_in[8] = r_eps (dead)
    const float* u_eps  = (const float*)d_in[9];
    const float* h_eps  = (const float*)d_in[10];
    float* out = (float*)d_out;

    cudaFuncSetAttribute(gemm_kernel, cudaFuncAttributeMaxDynamicSharedMemorySize, SMEM_BYTES);

    build_A_kernel<<<(MDIM * 1024) / 256, 256>>>(x, h_prev);
    build_Bt_kernel<<<dim3(128, 32, 2), dim3(32, 8)>>>(W_mu, W_rho, U_mu, U_rho, u_eps, h_eps);
    build_bias_kernel<<<8, 256>>>(b_mu, b_rho, u_eps, h_eps);

    gemm_kernel<<<dim3(NDIM / BNT, MDIM / BMT), 256, SMEM_BYTES>>>(h_prev, out);
}

// round 9
// speedup vs baseline: 6.1348x; 1.0442x over previous
#include <cuda_runtime.h>
#include <cuda_fp16.h>
#include <math.h>
#include <stdint.h>

// B=2048, D=H=1024.
// Fused: A=[x, h, x^2, h^2] (2048x4096) fp16,
//        Bt[n,k], n=2*j+g interleaved (g=0:u gate, 1:h gate), fp16, from
//        [W_mu;U_mu;eps*sp2(W_rho);eps*sp2(U_rho)] columns [1024,3072).
// arg = A @ Bt^T + bias ; u=sigmoid, hp=tanh, out = u*h_prev + (1-u)*hp.
// (r gate is dead code in the reference.)
// GEMM: single-product fp16 mma.sync m16n8k16 (fp32 accum), rel_err ~2e-4.
// R9: register double-buffered fragments (ldsm of ks+1 overlaps MMA of ks);
//     all preprocessing fused into one launch.

#define MDIM 2048
#define NDIM 2048
#define KDIM 4096
#define HDIM 1024

__device__ __align__(128) __half g_A[(size_t)MDIM * KDIM];
__device__ __align__(128) __half g_B[(size_t)NDIM * KDIM];
__device__ float g_bias[NDIM];

__device__ __forceinline__ float softplusf(float r) {
    return (r > 20.0f) ? r : log1pf(expf(r));
}

// ---------------------------------------------------------------------------
// Fused preprocessing: one launch.
//  blocks [0, 4096)      : build A (2048x512 __half2 units, 256 thr)
//  blocks [4096, 12288)  : build Bt (tiled transpose, 256 thr as 32x8)
//  blocks [12288, 12296) : bias
// ---------------------------------------------------------------------------

__global__ void prep_kernel(const float* __restrict__ x, const float* __restrict__ h,
                            const float* __restrict__ W_mu, const float* __restrict__ W_rho,
                            const float* __restrict__ U_mu, const float* __restrict__ U_rho,
                            const float* __restrict__ b_mu, const float* __restrict__ b_rho,
                            const float* __restrict__ u_eps, const float* __restrict__ h_eps) {
    const int bid = blockIdx.x;
    const int tid = threadIdx.x;

    if (bid < 4096) {
        // ---- build A: each thread handles 2 consecutive k ----
        int idx = bid * 256 + tid;          // over 2048*512
        int b = idx >> 9;
        int k2 = (idx & 511) << 1;          // even k
        float2 xv = *(const float2*)(x + (size_t)b * 1024 + k2);
        float2 hv = *(const float2*)(h + (size_t)b * 1024 + k2);
        __half2* row = (__half2*)(g_A + (size_t)b * KDIM);
        int p = k2 >> 1;
        row[p]        = __floats2half2_rn(xv.x, xv.y);
        row[512 + p]  = __floats2half2_rn(hv.x, hv.y);
        row[1024 + p] = __floats2half2_rn(xv.x * xv.x, xv.y * xv.y);
        row[1536 + p] = __floats2half2_rn(hv.x * hv.x, hv.y * hv.y);
    } else if (bid < 12288) {
        // ---- build Bt: tiled transpose ----
        __shared__ float tile[32][33];
        int b2 = bid - 4096;                 // 8192 blocks = 128 k-tiles x 32 j-tiles x 2 gates
        int kb = b2 & 127, jb = (b2 >> 7) & 31, g = b2 >> 12;
        int k0 = kb * 32, jj0 = jb * 32;
        int tx = tid & 31, ty = tid >> 5;    // 32 x 8
        int gcol = (g + 1) * 1024 + jj0 + tx;
#pragma unroll
        for (int i = 0; i < 4; ++i) {
            int k = k0 + ty + i * 8;
            float v;
            if (k < 1024)       v = W_mu[(size_t)k * 3072 + gcol];
            else if (k < 2048)  v = U_mu[(size_t)(k - 1024) * 3072 + gcol];
            else {
                float rho = (k < 3072) ? W_rho[(size_t)(k - 2048) * 3072 + gcol]
                                       : U_rho[(size_t)(k - 3072) * 3072 + gcol];
                float s = softplusf(rho);
                v = s * s;
            }
            tile[ty + i * 8][tx] = v;
        }
        __syncthreads();
        bool sigreg = (k0 >= 2048);
#pragma unroll
        for (int i = 0; i < 4; ++i) {
            int jj = jj0 + ty + i * 8;
            float v = tile[tx][ty + i * 8];          // source (k0+tx, jj)
            if (sigreg) v *= (g ? h_eps[jj] : u_eps[jj]);
            int n = 2 * jj + g;
            g_B[(size_t)n * KDIM + k0 + tx] = __float2half(v);
        }
    } else {
        // ---- bias ----
        int n = (bid - 12288) * 256 + tid;
        int jj = n >> 1, g = n & 1;
        int gcol = (g + 1) * 1024 + jj;
        float eps = g ? h_eps[jj] : u_eps[jj];
        g_bias[n] = b_mu[gcol] + eps * softplusf(b_rho[gcol]);
    }
}

// ---------------------------------------------------------------------------
// GEMM: 2048x2048x4096 fp16 via mma.sync m16n8k16, fp32 accum
// 128x128 tile, 256 threads, 8 warps (2 M x 4 N), warp tile 64x32
// BK=64, SW128 swizzle, 3 stages, 2 CTAs/SM, fragment double-buffering.
// ---------------------------------------------------------------------------

#define BMT 128
#define BNT 128
#define KT (KDIM / 64)           // 64 chunks of BK=64
#define TILE_B 16384             // 128 rows x 128B
#define A_OFF 0
#define B_OFF 16384
#define STG 32768
#define NSTG 3
#define SMEM_BYTES (NSTG * STG)  // 98304 -> 2 CTAs/SM

static __device__ __forceinline__ uint32_t smem_u32(const void* p) {
    uint32_t a;
    asm("{ .reg .u64 t; cvta.to.shared.u64 t, %1; cvt.u32.u64 %0, t; }" : "=r"(a) : "l"(p));
    return a;
}
static __device__ __forceinline__ void cp16(uint32_t saddr, const void* g) {
    asm volatile("cp.async.cg.shared.global [%0], [%1], 16;" :: "r"(saddr), "l"(g));
}
static __device__ __forceinline__ void cp_commit() {
    asm volatile("cp.async.commit_group;" ::: "memory");
}
template <int N> static __device__ __forceinline__ void cp_wait() {
    asm volatile("cp.async.wait_group %0;" :: "n"(N) : "memory");
}
static __device__ __forceinline__ void ldsm4(uint32_t* r, uint32_t addr) {
    asm volatile("ldmatrix.sync.aligned.m8n8.x4.shared.b16 {%0,%1,%2,%3}, [%4];"
                 : "=r"(r[0]), "=r"(r[1]), "=r"(r[2]), "=r"(r[3]) : "r"(addr));
}
static __device__ __forceinline__ void mma16816(float* c, const uint32_t* a, uint32_t b0, uint32_t b1) {
    asm volatile("mma.sync.aligned.m16n8k16.row.col.f32.f16.f16.f32 "
                 "{%0,%1,%2,%3}, {%4,%5,%6,%7}, {%8,%9}, {%0,%1,%2,%3};"
                 : "+f"(c[0]), "+f"(c[1]), "+f"(c[2]), "+f"(c[3])
                 : "r"(a[0]), "r"(a[1]), "r"(a[2]), "r"(a[3]), "r"(b0), "r"(b1));
}

__global__ __launch_bounds__(256, 2) void gemm_kernel(const float* __restrict__ h_prev,
                                                      float* __restrict__ out) {
    extern __shared__ char sm[];
    const uint32_t sbase = smem_u32(sm);

    const int tid  = threadIdx.x;
    const int lane = tid & 31, wid = tid >> 5;
    const int warp_m = wid & 1, warp_n = wid >> 1;   // 2 x 4
    const int bm = blockIdx.y, bn = blockIdx.x;

    const char* AG = (const char*)g_A + (size_t)(bm * BMT) * (KDIM * 2);
    const char* BG = (const char*)g_B + (size_t)(bn * BNT) * (KDIM * 2);

    // cp.async: per tile 1024 16B lines (128 rows x 8 segs); 4 lines/thread/tile.
    // Addressing recomputed per call to keep registers free for fragments.
    auto load_chunk = [&](int stage, int kt) {
        const uint32_t st = sbase + stage * STG;
        const size_t kb = (size_t)kt * 128;   // 64 elems * 2B
#pragma unroll
        for (int i = 0; i < 4; ++i) {
            int L = tid + i * 256;
            int row = L >> 3, seg = L & 7;
            uint32_t so = (uint32_t)(row * 128 + ((seg * 16) ^ ((row & 7) << 4)));
            size_t go = (size_t)row * (KDIM * 2) + seg * 16 + kb;
            cp16(st + A_OFF + so, AG + go);
            cp16(st + B_OFF + so, BG + go);
        }
        cp_commit();
    };

    float acc[4][4][4];
#pragma unroll
    for (int i = 0; i < 4; ++i)
#pragma unroll
        for (int j = 0; j < 4; ++j)
#pragma unroll
            for (int q = 0; q < 4; ++q) acc[i][j][q] = 0.0f;

    // ldmatrix row/col-base (SW128: koff ^= (row&7)<<4)
    const int arow_l = lane & 15;
    const uint32_t a_k0 = (uint32_t)((lane >> 4) * 16);
    const int brow_l = ((lane >> 4) << 3) + (lane & 7);
    const uint32_t b_k0 = (uint32_t)(((lane >> 3) & 1) * 16);

    auto load_frags = [&](uint32_t st, int ks, uint32_t af[4][4], uint32_t bf[2][4]) {
        const uint32_t ka = (uint32_t)(ks * 32);
#pragma unroll
        for (int p = 0; p < 2; ++p) {
            const int row = warp_n * 32 + p * 16 + brow_l;
            const uint32_t koff = (b_k0 + ka) ^ ((uint32_t)(row & 7) << 4);
            ldsm4(bf[p], st + B_OFF + (uint32_t)row * 128 + koff);
        }
#pragma unroll
        for (int mt = 0; mt < 4; ++mt) {
            const int row = warp_m * 64 + mt * 16 + arow_l;
            const uint32_t koff = (a_k0 + ka) ^ ((uint32_t)(row & 7) << 4);
            ldsm4(af[mt], st + A_OFF + (uint32_t)row * 128 + koff);
        }
    };

    load_chunk(0, 0);
    load_chunk(1, 1);

    uint32_t af[2][4][4], bf[2][2][4];

    for (int kt = 0; kt < KT; ++kt) {
        const int stage = kt % NSTG;
        if (kt >= KT - 1) cp_wait<0>(); else cp_wait<1>();
        __syncthreads();
        if (kt + 2 < KT) load_chunk((kt + 2) % NSTG, kt + 2);

        const uint32_t st = sbase + stage * STG;

        load_frags(st, 0, af[0], bf[0]);
#pragma unroll
        for (int ks = 0; ks < 4; ++ks) {
            const int cur = ks & 1;
            if (ks < 3) load_frags(st, ks + 1, af[cur ^ 1], bf[cur ^ 1]);
#pragma unroll
            for (int mt = 0; mt < 4; ++mt)
#pragma unroll
                for (int p = 0; p < 2; ++p) {
                    mma16816(acc[mt][2 * p],     af[cur][mt], bf[cur][p][0], bf[cur][p][1]);
                    mma16816(acc[mt][2 * p + 1], af[cur][mt], bf[cur][p][2], bf[cur][p][3]);
                }
        }
    }

    // Epilogue: adjacent accumulator column pair = (u-gate, h-gate) for one j.
    const int r_base = bm * BMT + warp_m * 64 + (lane >> 2);
#pragma unroll
    for (int mt = 0; mt < 4; ++mt) {
#pragma unroll
        for (int nt = 0; nt < 4; ++nt) {
            const int n0 = bn * BNT + warp_n * 32 + nt * 8 + (lane & 3) * 2;
            const float bu = g_bias[n0];
            const float bh = g_bias[n0 + 1];
            const int j = n0 >> 1;
#pragma unroll
            for (int hlf = 0; hlf < 2; ++hlf) {
                const int row = r_base + mt * 16 + hlf * 8;
                const float au  = acc[mt][nt][hlf * 2]     + bu;
                const float ahv = acc[mt][nt][hlf * 2 + 1] + bh;
                const float u  = 1.0f / (1.0f + __expf(-au));
                const float hp = tanhf(ahv);
                const size_t g = (size_t)row * HDIM + j;
                out[g] = u * h_prev[g] + (1.0f - u) * hp;
            }
        }
    }
}

// ---------------------------------------------------------------------------
// Launch
// ---------------------------------------------------------------------------

extern "C" void kernel_launch(void* const* d_in, const int* in_sizes, int n_in,
                              void* d_out, int out_size) {
    const float* x      = (const float*)d_in[0];
    const float* h_prev = (const float*)d_in[1];
    const float* W_mu   = (const float*)d_in[2];
    const float* W_rho  = (const float*)d_in[3];
    const float* U_mu   = (const float*)d_in[4];
    const float* U_rho  = (const float*)d_in[5];
    const float* b_mu   = (const float*)d_in[6];
    const float* b_rho  = (const float*)d_in[7];
    // d_in[8] = r_eps (dead)
    const float* u_eps  = (const float*)d_in[9];
    const float* h_eps  = (const float*)d_in[10];
    float* out = (float*)d_out;

    cudaFuncSetAttribute(gemm_kernel, cudaFuncAttributeMaxDynamicSharedMemorySize, SMEM_BYTES);

    prep_kernel<<<12296, 256>>>(x, h_prev, W_mu, W_rho, U_mu, U_rho, b_mu, b_rho, u_eps, h_eps);
    gemm_kernel<<<dim3(NDIM / BNT, MDIM / BMT), 256, SMEM_BYTES>>>(h_prev, out);
}

// round 10
// speedup vs baseline: 6.5048x; 1.0603x over previous
#include <cuda_runtime.h>
#include <cuda_fp16.h>
#include <math.h>
#include <stdint.h>

// B=2048, D=H=1024.
// Fused: A=[x, h, x^2, h^2] (2048x4096) fp16,
//        Bt[n,k], n=2*j+g interleaved (g=0:u gate, 1:h gate), fp16, from
//        [W_mu;U_mu;eps*sp2(W_rho);eps*sp2(U_rho)] columns [1024,3072).
// arg = A @ Bt^T + bias ; u=sigmoid, hp=tanh, out = u*h_prev + (1-u)*hp.
// (r gate is dead code in the reference.)
// GEMM: single-product fp16 mma.sync m16n8k16 (fp32 accum), rel_err ~2e-4.
// R10: k-loop unrolled by NSTG=3 -> compile-time stage bases (ALU cut,
//      wider ptxas scheduling window). Prep: A-build float4, B blocks first.

#define MDIM 2048
#define NDIM 2048
#define KDIM 4096
#define HDIM 1024

__device__ __align__(128) __half g_A[(size_t)MDIM * KDIM];
__device__ __align__(128) __half g_B[(size_t)NDIM * KDIM];
__device__ float g_bias[NDIM];

__device__ __forceinline__ float softplusf(float r) {
    return (r > 20.0f) ? r : log1pf(expf(r));
}

// ---------------------------------------------------------------------------
// Fused preprocessing: one launch.
//  blocks [0, 8192)      : build Bt (tiled transpose, 256 thr as 32x8)
//  blocks [8192, 10240)  : build A (float4: 4 elems/thread)
//  blocks [10240, 10248) : bias
// ---------------------------------------------------------------------------

__global__ void prep_kernel(const float* __restrict__ x, const float* __restrict__ h,
                            const float* __restrict__ W_mu, const float* __restrict__ W_rho,
                            const float* __restrict__ U_mu, const float* __restrict__ U_rho,
                            const float* __restrict__ b_mu, const float* __restrict__ b_rho,
                            const float* __restrict__ u_eps, const float* __restrict__ h_eps) {
    const int bid = blockIdx.x;
    const int tid = threadIdx.x;

    if (bid < 8192) {
        // ---- build Bt: tiled transpose (128 k-tiles x 32 j-tiles x 2 gates) ----
        __shared__ float tile[32][33];
        int kb = bid & 127, jb = (bid >> 7) & 31, g = bid >> 12;
        int k0 = kb * 32, jj0 = jb * 32;
        int tx = tid & 31, ty = tid >> 5;    // 32 x 8
        int gcol = (g + 1) * 1024 + jj0 + tx;
#pragma unroll
        for (int i = 0; i < 4; ++i) {
            int k = k0 + ty + i * 8;
            float v;
            if (k < 1024)       v = W_mu[(size_t)k * 3072 + gcol];
            else if (k < 2048)  v = U_mu[(size_t)(k - 1024) * 3072 + gcol];
            else {
                float rho = (k < 3072) ? W_rho[(size_t)(k - 2048) * 3072 + gcol]
                                       : U_rho[(size_t)(k - 3072) * 3072 + gcol];
                float s = softplusf(rho);
                v = s * s;
            }
            tile[ty + i * 8][tx] = v;
        }
        __syncthreads();
        bool sigreg = (k0 >= 2048);
#pragma unroll
        for (int i = 0; i < 4; ++i) {
            int jj = jj0 + ty + i * 8;
            float v = tile[tx][ty + i * 8];          // source (k0+tx, jj)
            if (sigreg) v *= (g ? h_eps[jj] : u_eps[jj]);
            int n = 2 * jj + g;
            g_B[(size_t)n * KDIM + k0 + tx] = __float2half(v);
        }
    } else if (bid < 10240) {
        // ---- build A: float4, 4 consecutive k per thread ----
        int idx = (bid - 8192) * 256 + tid;   // over 2048*256
        int b = idx >> 8;
        int k4 = (idx & 255) << 2;
        float4 xv = *(const float4*)(x + (size_t)b * 1024 + k4);
        float4 hv = *(const float4*)(h + (size_t)b * 1024 + k4);
        __half2* row = (__half2*)(g_A + (size_t)b * KDIM);
        int p = k4 >> 1;
        row[p]          = __floats2half2_rn(xv.x, xv.y);
        row[p + 1]      = __floats2half2_rn(xv.z, xv.w);
        row[512 + p]    = __floats2half2_rn(hv.x, hv.y);
        row[512 + p + 1]= __floats2half2_rn(hv.z, hv.w);
        row[1024 + p]   = __floats2half2_rn(xv.x * xv.x, xv.y * xv.y);
        row[1024 + p+1] = __floats2half2_rn(xv.z * xv.z, xv.w * xv.w);
        row[1536 + p]   = __floats2half2_rn(hv.x * hv.x, hv.y * hv.y);
        row[1536 + p+1] = __floats2half2_rn(hv.z * hv.z, hv.w * hv.w);
    } else {
        // ---- bias ----
        int n = (bid - 10240) * 256 + tid;
        int jj = n >> 1, g = n & 1;
        int gcol = (g + 1) * 1024 + jj;
        float eps = g ? h_eps[jj] : u_eps[jj];
        g_bias[n] = b_mu[gcol] + eps * softplusf(b_rho[gcol]);
    }
}

// ---------------------------------------------------------------------------
// GEMM: 2048x2048x4096 fp16 via mma.sync m16n8k16, fp32 accum
// 128x128 tile, 256 threads, 8 warps (2 M x 4 N), warp tile 64x32
// BK=64, SW128 swizzle, 3 stages (compile-time bases), 2 CTAs/SM.
// ---------------------------------------------------------------------------

#define BMT 128
#define BNT 128
#define KT (KDIM / 64)           // 64 chunks of BK=64
#define TILE_B 16384             // 128 rows x 128B
#define A_OFF 0
#define B_OFF 16384
#define STG 32768
#define NSTG 3
#define SMEM_BYTES (NSTG * STG)  // 98304 -> 2 CTAs/SM

static __device__ __forceinline__ uint32_t smem_u32(const void* p) {
    uint32_t a;
    asm("{ .reg .u64 t; cvta.to.shared.u64 t, %1; cvt.u32.u64 %0, t; }" : "=r"(a) : "l"(p));
    return a;
}
static __device__ __forceinline__ void cp16(uint32_t saddr, const void* g) {
    asm volatile("cp.async.cg.shared.global [%0], [%1], 16;" :: "r"(saddr), "l"(g));
}
static __device__ __forceinline__ void cp_commit() {
    asm volatile("cp.async.commit_group;" ::: "memory");
}
template <int N> static __device__ __forceinline__ void cp_wait() {
    asm volatile("cp.async.wait_group %0;" :: "n"(N) : "memory");
}
static __device__ __forceinline__ void ldsm4(uint32_t* r, uint32_t addr) {
    asm volatile("ldmatrix.sync.aligned.m8n8.x4.shared.b16 {%0,%1,%2,%3}, [%4];"
                 : "=r"(r[0]), "=r"(r[1]), "=r"(r[2]), "=r"(r[3]) : "r"(addr));
}
static __device__ __forceinline__ void mma16816(float* c, const uint32_t* a, uint32_t b0, uint32_t b1) {
    asm volatile("mma.sync.aligned.m16n8k16.row.col.f32.f16.f16.f32 "
                 "{%0,%1,%2,%3}, {%4,%5,%6,%7}, {%8,%9}, {%0,%1,%2,%3};"
                 : "+f"(c[0]), "+f"(c[1]), "+f"(c[2]), "+f"(c[3])
                 : "r"(a[0]), "r"(a[1]), "r"(a[2]), "r"(a[3]), "r"(b0), "r"(b1));
}

__global__ __launch_bounds__(256, 2) void gemm_kernel(const float* __restrict__ h_prev,
                                                      float* __restrict__ out) {
    extern __shared__ char sm[];
    const uint32_t sbase = smem_u32(sm);

    const int tid  = threadIdx.x;
    const int lane = tid & 31, wid = tid >> 5;
    const int warp_m = wid & 1, warp_n = wid >> 1;   // 2 x 4
    const int bm = blockIdx.y, bn = blockIdx.x;

    const char* AG = (const char*)g_A + (size_t)(bm * BMT) * (KDIM * 2);
    const char* BG = (const char*)g_B + (size_t)(bn * BNT) * (KDIM * 2);

    auto load_chunk = [&](int stage, int kt) {
        const uint32_t st = sbase + stage * STG;
        const size_t kb = (size_t)kt * 128;   // 64 elems * 2B
#pragma unroll
        for (int i = 0; i < 4; ++i) {
            int L = tid + i * 256;
            int row = L >> 3, seg = L & 7;
            uint32_t so = (uint32_t)(row * 128 + ((seg * 16) ^ ((row & 7) << 4)));
            size_t go = (size_t)row * (KDIM * 2) + seg * 16 + kb;
            cp16(st + A_OFF + so, AG + go);
            cp16(st + B_OFF + so, BG + go);
        }
        cp_commit();
    };

    float acc[4][4][4];
#pragma unroll
    for (int i = 0; i < 4; ++i)
#pragma unroll
        for (int j = 0; j < 4; ++j)
#pragma unroll
            for (int q = 0; q < 4; ++q) acc[i][j][q] = 0.0f;

    // ldmatrix row/col-base (SW128: koff ^= (row&7)<<4)
    const int arow_l = lane & 15;
    const uint32_t a_k0 = (uint32_t)((lane >> 4) * 16);
    const int brow_l = ((lane >> 4) << 3) + (lane & 7);
    const uint32_t b_k0 = (uint32_t)(((lane >> 3) & 1) * 16);

    uint32_t af[2][4][4], bf[2][2][4];

    auto load_frags = [&](uint32_t st, int ks, int buf) {
        const uint32_t ka = (uint32_t)(ks * 32);
#pragma unroll
        for (int p = 0; p < 2; ++p) {
            const int row = warp_n * 32 + p * 16 + brow_l;
            const uint32_t koff = (b_k0 + ka) ^ ((uint32_t)(row & 7) << 4);
            ldsm4(bf[buf][p], st + B_OFF + (uint32_t)row * 128 + koff);
        }
#pragma unroll
        for (int mt = 0; mt < 4; ++mt) {
            const int row = warp_m * 64 + mt * 16 + arow_l;
            const uint32_t koff = (a_k0 + ka) ^ ((uint32_t)(row & 7) << 4);
            ldsm4(af[buf][mt], st + A_OFF + (uint32_t)row * 128 + koff);
        }
    };

    auto compute_chunk = [&](uint32_t st) {
        load_frags(st, 0, 0);
#pragma unroll
        for (int ks = 0; ks < 4; ++ks) {
            const int cur = ks & 1;
            if (ks < 3) load_frags(st, ks + 1, cur ^ 1);
#pragma unroll
            for (int mt = 0; mt < 4; ++mt)
#pragma unroll
                for (int p = 0; p < 2; ++p) {
                    mma16816(acc[mt][2 * p],     af[cur][mt], bf[cur][p][0], bf[cur][p][1]);
                    mma16816(acc[mt][2 * p + 1], af[cur][mt], bf[cur][p][2], bf[cur][p][3]);
                }
        }
    };

    load_chunk(0, 0);
    load_chunk(1, 1);

    // Unrolled-by-NSTG main loop: stage index is compile-time per body.
#pragma unroll 1
    for (int kt = 0; kt < KT - 1; kt += 3) {     // 21 iterations, kt = 0,3,...,60
        // body stage 0
        cp_wait<1>();
        __syncthreads();
        load_chunk(2, kt + 2);
        compute_chunk(sbase + 0 * STG);
        // body stage 1
        cp_wait<1>();
        __syncthreads();
        load_chunk(0, kt + 3);
        compute_chunk(sbase + 1 * STG);
        // body stage 2
        cp_wait<1>();
        __syncthreads();
        if (kt + 4 < KT) load_chunk(1, kt + 4);
        compute_chunk(sbase + 2 * STG);
    }
    // tail: kt = 63, stage 0
    cp_wait<0>();
    __syncthreads();
    compute_chunk(sbase + 0 * STG);

    // Epilogue: adjacent accumulator column pair = (u-gate, h-gate) for one j.
    const int r_base = bm * BMT + warp_m * 64 + (lane >> 2);
#pragma unroll
    for (int mt = 0; mt < 4; ++mt) {
#pragma unroll
        for (int nt = 0; nt < 4; ++nt) {
            const int n0 = bn * BNT + warp_n * 32 + nt * 8 + (lane & 3) * 2;
            const float bu = g_bias[n0];
            const float bh = g_bias[n0 + 1];
            const int j = n0 >> 1;
#pragma unroll
            for (int hlf = 0; hlf < 2; ++hlf) {
                const int row = r_base + mt * 16 + hlf * 8;
                const float au  = acc[mt][nt][hlf * 2]     + bu;
                const float ahv = acc[mt][nt][hlf * 2 + 1] + bh;
                const float u  = 1.0f / (1.0f + __expf(-au));
                const float hp = tanhf(ahv);
                const size_t g = (size_t)row * HDIM + j;
                out[g] = u * h_prev[g] + (1.0f - u) * hp;
            }
        }
    }
}

// ---------------------------------------------------------------------------
// Launch
// ---------------------------------------------------------------------------

extern "C" void kernel_launch(void* const* d_in, const int* in_sizes, int n_in,
                              void* d_out, int out_size) {
    const float* x      = (const float*)d_in[0];
    const float* h_prev = (const float*)d_in[1];
    const float* W_mu   = (const float*)d_in[2];
    const float* W_rho  = (const float*)d_in[3];
    const float* U_mu   = (const float*)d_in[4];
    const float* U_rho  = (const float*)d_in[5];
    const float* b_mu   = (const float*)d_in[6];
    const float* b_rho  = (const float*)d_in[7];
    // d_in[8] = r_eps (dead)
    const float* u_eps  = (const float*)d_in[9];
    const float* h_eps  = (const float*)d_in[10];
    float* out = (float*)d_out;

    cudaFuncSetAttribute(gemm_kernel, cudaFuncAttributeMaxDynamicSharedMemorySize, SMEM_BYTES);

    prep_kernel<<<10248, 256>>>(x, h_prev, W_mu, W_rho, U_mu, U_rho, b_mu, b_rho, u_eps, h_eps);
    gemm_kernel<<<dim3(NDIM / BNT, MDIM / BMT), 256, SMEM_BYTES>>>(h_prev, out);
}